// round 13
// baseline (speedup 1.0000x reference)
#include <cuda_runtime.h>
#include <cuda_bf16.h>
#include <math.h>
#include <stdint.h>

#define NN    32768
#define DD    128
#define EE    262144
#define MMOT  131072
#define NG    32
#define PW    896      // packed width: Q2[0:128) K2[128:256) Q3[256:512) K3[512:768) Qm[768:896)

// ---------------- scratch (device globals; no allocs allowed) ----------------
__device__ float          d_mu[NN];
__device__ float          d_rstd[NN];
__device__ __nv_bfloat16  d_Gh[NN * DD];
__device__ __nv_bfloat16  d_Gl[NN * DD];
__device__ float          d_P[NN * PW];     // fp32 projections
__device__ float          d_gP[NN * PW];    // fp32 gradient accumulator
__device__ float          d_gG[NN * DD];
__device__ __nv_bfloat16  d_Wh[PW * DD];    // [j][d]
__device__ __nv_bfloat16  d_Wl[PW * DD];
__device__ __nv_bfloat16  d_WTh[DD * PW];   // [d][j]
__device__ __nv_bfloat16  d_WTl[DD * PW];
__device__ float          d_Km[4096];       // [h][k][z] = [2][32][64]
__device__ float          d_w2[EE * 2];     // exp(s2)
__device__ float          d_w3[MMOT * 2];   // exp(s3)
__device__ float          d_qk3[MMOT * 4];
__device__ float          d_tv3[MMOT * 4];
__device__ float          d_z2[NN * 2];
__device__ float          d_z3[NN * 2];
__device__ float          d_Eg[NG];

// ---------------- helpers ----------------
__device__ __forceinline__ uint32_t smem_to_u32(const void* p) {
    uint32_t a;
    asm("{ .reg .u64 t; cvta.to.shared.u64 t, %1; cvt.u32.u64 %0, t; }" : "=r"(a) : "l"(p));
    return a;
}
__device__ __forceinline__ float wsum(float v) {
#pragma unroll
    for (int o = 16; o; o >>= 1) v += __shfl_xor_sync(0xffffffffu, v, o);
    return v;
}
__device__ __forceinline__ void red4(float* a, float x, float y, float z, float w) {
    asm volatile("red.global.add.v4.f32 [%0], {%1,%2,%3,%4};"
                 :: "l"(__cvta_generic_to_global(a)), "f"(x), "f"(y), "f"(z), "f"(w) : "memory");
}
__device__ __forceinline__ void red2(float* a, float x, float y) {
    asm volatile("red.global.add.v2.f32 [%0], {%1,%2};"
                 :: "l"(__cvta_generic_to_global(a)), "f"(x), "f"(y) : "memory");
}
__device__ __forceinline__ uint32_t pack_bf2(__nv_bfloat16 a, __nv_bfloat16 b) {
    __nv_bfloat162 p = __halves2bfloat162(a, b);
    return *(uint32_t*)&p;
}
__device__ __forceinline__ void ldsm4(uint32_t* r, uint32_t addr) {
    asm volatile("ldmatrix.sync.aligned.m8n8.x4.shared.b16 {%0,%1,%2,%3}, [%4];"
                 : "=r"(r[0]), "=r"(r[1]), "=r"(r[2]), "=r"(r[3]) : "r"(addr));
}
__device__ __forceinline__ void mma16816(float* c, const uint32_t* a, const uint32_t* b) {
    asm volatile("mma.sync.aligned.m16n8k16.row.col.f32.bf16.bf16.f32 "
                 "{%0,%1,%2,%3}, {%4,%5,%6,%7}, {%8,%9}, {%0,%1,%2,%3};"
                 : "+f"(c[0]), "+f"(c[1]), "+f"(c[2]), "+f"(c[3])
                 : "r"(a[0]), "r"(a[1]), "r"(a[2]), "r"(a[3]), "r"(b[0]), "r"(b[1]));
}

// ---------------- layernorm forward -> G split into bf16 hi/lo ----------------
__global__ __launch_bounds__(256) void ln_fwd(const float* __restrict__ X,
                                              const float* __restrict__ gam,
                                              const float* __restrict__ bet) {
    int w = threadIdx.x >> 5, lane = threadIdx.x & 31;
    int n = blockIdx.x * 8 + w;
    float4 x = *(const float4*)&X[n * DD + lane * 4];
    float mu = wsum(x.x + x.y + x.z + x.w) * (1.0f / 128.0f);
    float dx0 = x.x - mu, dx1 = x.y - mu, dx2 = x.z - mu, dx3 = x.w - mu;
    float v = wsum(dx0 * dx0 + dx1 * dx1 + dx2 * dx2 + dx3 * dx3) * (1.0f / 128.0f);
    float rstd = rsqrtf(v + 1e-5f);
    float4 g = *(const float4*)&gam[lane * 4];
    float4 b = *(const float4*)&bet[lane * 4];
    float o0 = g.x * dx0 * rstd + b.x;
    float o1 = g.y * dx1 * rstd + b.y;
    float o2 = g.z * dx2 * rstd + b.z;
    float o3 = g.w * dx3 * rstd + b.w;
    __nv_bfloat16 h0 = __float2bfloat16(o0), h1 = __float2bfloat16(o1);
    __nv_bfloat16 h2 = __float2bfloat16(o2), h3 = __float2bfloat16(o3);
    __nv_bfloat16 l0 = __float2bfloat16(o0 - __bfloat162float(h0));
    __nv_bfloat16 l1 = __float2bfloat16(o1 - __bfloat162float(h1));
    __nv_bfloat16 l2 = __float2bfloat16(o2 - __bfloat162float(h2));
    __nv_bfloat16 l3 = __float2bfloat16(o3 - __bfloat162float(h3));
    *(uint2*)&d_Gh[n * DD + lane * 4] = make_uint2(pack_bf2(h0, h1), pack_bf2(h2, h3));
    *(uint2*)&d_Gl[n * DD + lane * 4] = make_uint2(pack_bf2(l0, l1), pack_bf2(l2, l3));
    if (lane == 0) { d_mu[n] = mu; d_rstd[n] = rstd; }
}

// ---------------- pack weights (hi/lo bf16, direct + transposed) ----------------
__global__ void prep_wcat(const float* __restrict__ WQ2, const float* __restrict__ WK2,
                          const float* __restrict__ WQ3, const float* __restrict__ WK3,
                          const float* __restrict__ WQm) {
    int i = blockIdx.x * 256 + threadIdx.x;
    if (i >= PW * DD) return;
    int j = i >> 7, d = i & 127;
    float v;
    if (j < 128)      v = WQ2[j * 128 + d];
    else if (j < 256) v = WK2[(j - 128) * 128 + d];
    else if (j < 512) v = WQ3[(j - 256) * 128 + d];
    else if (j < 768) v = WK3[(j - 512) * 128 + d];
    else              v = WQm[(j - 768) * 128 + d];
    __nv_bfloat16 h = __float2bfloat16(v);
    __nv_bfloat16 l = __float2bfloat16(v - __bfloat162float(h));
    d_Wh[i] = h; d_Wl[i] = l;
    d_WTh[d * PW + j] = h; d_WTl[d * PW + j] = l;
}

// ---------------- Km = B_mem @ W_Km^T : [2][32][64] ----------------
__global__ void km_kernel(const float* __restrict__ Bm, const float* __restrict__ WKm) {
    for (int i = threadIdx.x; i < 4096; i += 256) {
        int h = i >> 11, k = (i >> 6) & 31, z = i & 63;
        const float* brow = &Bm[k * 128];
        const float* wrow = &WKm[(h * 64 + z) * 128];
        float acc = 0.f;
#pragma unroll
        for (int dd = 0; dd < 128; dd += 4) {
            float4 b4 = *(const float4*)&brow[dd];
            float4 w4 = *(const float4*)&wrow[dd];
            acc += b4.x * w4.x + b4.y * w4.y + b4.z * w4.z + b4.w * w4.w;
        }
        d_Km[i] = acc;
    }
}

// ---------------- mma.sync GEMM: C[128,128] tile = A[128,K] @ B[128,K]^T ----------------
// bf16 split precision: C = Ah@Bh^T + Ah@Bl^T + Al@Bh^T, fp32 accumulate.
// smem tiles [128][72] bf16 (row stride 144B); K chunked by 64.
// AFP32: A operand fp32 in gmem, split hi/lo in registers (no conversion pass).
#define TILEB 18432   // 128 * 72 * 2

__device__ __forceinline__ void ld_tile64(const __nv_bfloat16* __restrict__ src, int ld,
                                          char* dst, int tid) {
#pragma unroll
    for (int it = 0; it < 4; it++) {
        int c = it * 256 + tid;            // 1024 chunks of 16B
        int r = c >> 3, c8 = (c & 7) << 3; // row, bf16 col
        *(uint4*)(dst + r * 144 + (c8 << 1)) = *(const uint4*)&src[(size_t)r * ld + c8];
    }
}

__device__ __forceinline__ void ld_tile64_f32(const float* __restrict__ src, int ld,
                                              char* dh, char* dl, int tid) {
#pragma unroll
    for (int it = 0; it < 4; it++) {
        int c = it * 256 + tid;
        int r = c >> 3, c8 = (c & 7) << 3;
        float4 v0 = *(const float4*)&src[(size_t)r * ld + c8];
        float4 v1 = *(const float4*)&src[(size_t)r * ld + c8 + 4];
        float f[8] = {v0.x, v0.y, v0.z, v0.w, v1.x, v1.y, v1.z, v1.w};
        uint32_t hw[4], lw[4];
#pragma unroll
        for (int j = 0; j < 4; j++) {
            __nv_bfloat16 ha = __float2bfloat16(f[2 * j]);
            __nv_bfloat16 hb = __float2bfloat16(f[2 * j + 1]);
            __nv_bfloat16 la = __float2bfloat16(f[2 * j] - __bfloat162float(ha));
            __nv_bfloat16 lb = __float2bfloat16(f[2 * j + 1] - __bfloat162float(hb));
            hw[j] = pack_bf2(ha, hb);
            lw[j] = pack_bf2(la, lb);
        }
        *(uint4*)(dh + r * 144 + (c8 << 1)) = make_uint4(hw[0], hw[1], hw[2], hw[3]);
        *(uint4*)(dl + r * 144 + (c8 << 1)) = make_uint4(lw[0], lw[1], lw[2], lw[3]);
    }
}

template <bool AFP32>
__global__ __launch_bounds__(256) void gemm_mma(
    const void* __restrict__ Ah_, const void* __restrict__ Al_, int lda,
    const __nv_bfloat16* __restrict__ Bh, const __nv_bfloat16* __restrict__ Bl, int ldb,
    float* __restrict__ C, int ldc, int Kdim)
{
    extern __shared__ __align__(16) char smem[];
    int tid = threadIdx.x, wid = tid >> 5, lane = tid & 31;
    int row0 = blockIdx.x * 128, col0 = blockIdx.y * 128;
    Bh += (size_t)col0 * ldb; Bl += (size_t)col0 * ldb;
    uint32_t sb = smem_to_u32(smem);

    int wm = (wid & 1) * 64;       // warp row base
    int wn = (wid >> 1) * 32;      // warp col base

    uint32_t aoff[4], boff[2];
#pragma unroll
    for (int mt = 0; mt < 4; mt++)
        aoff[mt] = (uint32_t)((wm + mt * 16 + (lane & 15)) * 144 + ((lane >> 4) << 4));
#pragma unroll
    for (int p = 0; p < 2; p++)
        boff[p] = (uint32_t)((wn + p * 16 + ((lane >> 4) << 3) + (lane & 7)) * 144 +
                             (((lane >> 3) & 1) << 4));

    float acc[4][4][4];
#pragma unroll
    for (int i = 0; i < 4; i++)
#pragma unroll
        for (int j = 0; j < 4; j++)
#pragma unroll
            for (int k = 0; k < 4; k++) acc[i][j][k] = 0.f;

    for (int kc = 0; kc < Kdim; kc += 64) {
        if (AFP32) {
            const float* A = (const float*)Ah_ + (size_t)row0 * lda;
            ld_tile64_f32(A + kc, lda, smem + 0 * TILEB, smem + 1 * TILEB, tid);
        } else {
            const __nv_bfloat16* Ah = (const __nv_bfloat16*)Ah_ + (size_t)row0 * lda;
            const __nv_bfloat16* Al = (const __nv_bfloat16*)Al_ + (size_t)row0 * lda;
            ld_tile64(Ah + kc, lda, smem + 0 * TILEB, tid);
            ld_tile64(Al + kc, lda, smem + 1 * TILEB, tid);
        }
        ld_tile64(Bh + kc, ldb, smem + 2 * TILEB, tid);
        ld_tile64(Bl + kc, ldb, smem + 3 * TILEB, tid);
        __syncthreads();
#pragma unroll
        for (int ks = 0; ks < 4; ks++) {
            uint32_t ksb = ks * 32;  // 16 bf16 = 32 bytes
            uint32_t ah[4][4], al[4][4], bh[4][2], bl[4][2];
#pragma unroll
            for (int mt = 0; mt < 4; mt++) ldsm4(ah[mt], sb + 0 * TILEB + aoff[mt] + ksb);
#pragma unroll
            for (int p = 0; p < 2; p++) {
                uint32_t r4[4];
                ldsm4(r4, sb + 2 * TILEB + boff[p] + ksb);
                bh[2 * p][0] = r4[0]; bh[2 * p][1] = r4[1];
                bh[2 * p + 1][0] = r4[2]; bh[2 * p + 1][1] = r4[3];
            }
#pragma unroll
            for (int mt = 0; mt < 4; mt++)
#pragma unroll
                for (int nt = 0; nt < 4; nt++) mma16816(acc[mt][nt], ah[mt], bh[nt]);
#pragma unroll
            for (int p = 0; p < 2; p++) {
                uint32_t r4[4];
                ldsm4(r4, sb + 3 * TILEB + boff[p] + ksb);
                bl[2 * p][0] = r4[0]; bl[2 * p][1] = r4[1];
                bl[2 * p + 1][0] = r4[2]; bl[2 * p + 1][1] = r4[3];
            }
#pragma unroll
            for (int mt = 0; mt < 4; mt++)
#pragma unroll
                for (int nt = 0; nt < 4; nt++) mma16816(acc[mt][nt], ah[mt], bl[nt]);
#pragma unroll
            for (int mt = 0; mt < 4; mt++) ldsm4(al[mt], sb + 1 * TILEB + aoff[mt] + ksb);
#pragma unroll
            for (int mt = 0; mt < 4; mt++)
#pragma unroll
                for (int nt = 0; nt < 4; nt++) mma16816(acc[mt][nt], al[mt], bh[nt]);
        }
        __syncthreads();
    }

    // epilogue
    int g = lane >> 2, tg = lane & 3;
#pragma unroll
    for (int mt = 0; mt < 4; mt++) {
        int r = row0 + wm + mt * 16 + g;
#pragma unroll
        for (int nt = 0; nt < 4; nt++) {
            int cg = col0 + wn + nt * 8 + tg * 2;
            *(float2*)&C[(size_t)r * ldc + cg] = make_float2(acc[mt][nt][0], acc[mt][nt][1]);
            *(float2*)&C[(size_t)(r + 8) * ldc + cg] = make_float2(acc[mt][nt][2], acc[mt][nt][3]);
        }
    }
}

// ---------------- pair forward: w2 = exp(s2), z2 += w2 (warp per edge) ----------------
__global__ __launch_bounds__(256) void s2_fwd(const int* __restrict__ c2, const int* __restrict__ u2,
                                              const float* __restrict__ a2) {
    int e = blockIdx.x * 8 + (threadIdx.x >> 5);
    int lane = threadIdx.x & 31;
    int c = c2[e], u = u2[e];
    float4 q = *(const float4*)&d_P[(size_t)c * PW + lane * 4];
    float4 k = *(const float4*)&d_P[(size_t)u * PW + 128 + lane * 4];
    float p = q.x * k.x + q.y * k.y + q.z * k.z + q.w * k.w;
    p += __shfl_down_sync(0xffffffffu, p, 8);
    p += __shfl_down_sync(0xffffffffu, p, 4);
    p += __shfl_down_sync(0xffffffffu, p, 2);
    p += __shfl_down_sync(0xffffffffu, p, 1);
    if ((lane & 15) == 0) {
        int h = lane >> 4;
        float s = p * 0.125f + a2[e * 2 + h];
        float w = __expf(s);
        d_w2[e * 2 + h] = w;
        atomicAdd(&d_z2[c * 2 + h], w);
    }
}

// ---------------- motif forward (warp per motif) ----------------
__global__ __launch_bounds__(256) void s3_fwd(const int* __restrict__ c3, const int* __restrict__ u3,
                                              const int* __restrict__ v3, const int* __restrict__ tt,
                                              const float* __restrict__ Tt) {
    int m = blockIdx.x * 8 + (threadIdx.x >> 5);
    int lane = threadIdx.x & 31;
    int c = c3[m], u = u3[m], v = v3[m], t = tt[m];
    const float* Q  = &d_P[(size_t)c * PW + 256];
    const float* KU = &d_P[(size_t)u * PW + 512];
    const float* KV = &d_P[(size_t)v * PW + 512];
    const float* T  = &Tt[t * 256];
    float qk[4], tv[4];
#pragma unroll
    for (int hr = 0; hr < 4; hr++) {
        int off = hr * 64 + lane * 2;
        float2 qv  = *(const float2*)&Q[off];
        float2 kuv = *(const float2*)&KU[off];
        float2 kvv = *(const float2*)&KV[off];
        float2 tvv = *(const float2*)&T[off];
        qk[hr] = qv.x * kuv.x + qv.y * kuv.y;
        tv[hr] = tvv.x * kvv.x + tvv.y * kvv.y;
    }
#pragma unroll
    for (int hr = 0; hr < 4; hr++) { qk[hr] = wsum(qk[hr]); tv[hr] = wsum(tv[hr]); }
    if (lane == 0) {
#pragma unroll
        for (int hr = 0; hr < 4; hr++) { d_qk3[m * 4 + hr] = qk[hr]; d_tv3[m * 4 + hr] = tv[hr]; }
#pragma unroll
        for (int h = 0; h < 2; h++) {
            float s = (qk[h * 2] * tv[h * 2] + qk[h * 2 + 1] * tv[h * 2 + 1]) * (1.0f / 64.0f);
            float w = __expf(s);
            d_w3[m * 2 + h] = w;
            atomicAdd(&d_z3[c * 2 + h], w);
        }
    }
}

// ---------------- per-node: memory term (fwd+bwd) + energies -> Eg ----------------
__global__ __launch_bounds__(128) void node_energy(const float* __restrict__ X,
                                                   const int* __restrict__ batch) {
    __shared__ float sKm[2 * 32 * 65];
    __shared__ float sQm[4][128];
    __shared__ float sPm[4][2][32];
    int tid = threadIdx.x;
    int w = tid >> 5, lane = tid & 31;
    for (int i = tid; i < 4096; i += 128) {
        int h = i >> 11, k = (i >> 6) & 31, z = i & 63;
        sKm[(h * 32 + k) * 65 + z] = d_Km[i];
    }
    __syncthreads();
    int n = blockIdx.x * 4 + w;
    *(float4*)&sQm[w][lane * 4] = *(const float4*)&d_P[(size_t)n * PW + 768 + lane * 4];
    __syncwarp();
    float smv[2];
#pragma unroll
    for (int h = 0; h < 2; h++) {
        const float* kmrow = &sKm[(h * 32 + lane) * 65];
        const float* qrow = &sQm[w][h * 64];
        float acc = 0.f;
#pragma unroll
        for (int z = 0; z < 64; z++) acc += qrow[z] * kmrow[z];
        smv[h] = acc * 0.125f;
    }
    float e_mem = 0.f;
#pragma unroll
    for (int h = 0; h < 2; h++) {
        float mx = smv[h];
#pragma unroll
        for (int o = 16; o; o >>= 1) mx = fmaxf(mx, __shfl_xor_sync(0xffffffffu, mx, o));
        float ex = __expf(smv[h] - mx);
        float zs = wsum(ex);
        e_mem -= (mx + logf(zs));          // lamm = bm = 1
        sPm[w][h][lane] = ex / zs;
    }
    __syncwarp();
#pragma unroll
    for (int h = 0; h < 2; h++)
#pragma unroll
        for (int t2 = 0; t2 < 2; t2++) {
            int z = lane + 32 * t2;
            float g = 0.f;
#pragma unroll
            for (int k = 0; k < 32; k++) g += sPm[w][h][k] * sKm[(h * 32 + k) * 65 + z];
            d_gP[(size_t)n * PW + 768 + h * 64 + z] = -0.125f * g;
        }
    float4 xv = *(const float4*)&X[n * DD + lane * 4];
    float xs = wsum(xv.x * xv.x + xv.y * xv.y + xv.z * xv.z + xv.w * xv.w);
    if (lane == 0) {
        float e = 0.5f * xs + e_mem;
#pragma unroll
        for (int h = 0; h < 2; h++) {
            float z2v = d_z2[n * 2 + h];
            if (z2v > 0.f) e -= logf(z2v);            // lam2 = 1
            float z3v = d_z3[n * 2 + h];
            if (z3v > 0.f) e -= 0.5f * logf(z3v);     // lam3 = 0.5
        }
        atomicAdd(&d_Eg[batch[n]], e);
    }
}

// ---------------- pair backward (warp per edge) ----------------
__global__ __launch_bounds__(256) void pair_bwd(const int* __restrict__ c2, const int* __restrict__ u2) {
    int e = blockIdx.x * 8 + (threadIdx.x >> 5);
    int lane = threadIdx.x & 31;
    int c = c2[e], u = u2[e];
    int h = lane >> 4;
    float p = d_w2[e * 2 + h] / d_z2[c * 2 + h];
    float cf = -0.125f * p;                       // -lam2 * p / sqrt(HD)
    float4 q = *(const float4*)&d_P[(size_t)c * PW + lane * 4];
    float4 k = *(const float4*)&d_P[(size_t)u * PW + 128 + lane * 4];
    red4(&d_gP[(size_t)c * PW + lane * 4], cf * k.x, cf * k.y, cf * k.z, cf * k.w);
    red4(&d_gP[(size_t)u * PW + 128 + lane * 4], cf * q.x, cf * q.y, cf * q.z, cf * q.w);
}

// ---------------- motif backward (warp per motif) ----------------
__global__ __launch_bounds__(256) void motif_bwd(const int* __restrict__ c3, const int* __restrict__ u3,
                                                 const int* __restrict__ v3, const int* __restrict__ tt,
                                                 const float* __restrict__ Tt) {
    int m = blockIdx.x * 8 + (threadIdx.x >> 5);
    int lane = threadIdx.x & 31;
    int c = c3[m], u = u3[m], v = v3[m], t = tt[m];
    float dqk[4], dtv[4];
#pragma unroll
    for (int h = 0; h < 2; h++) {
        float p = d_w3[m * 2 + h] / d_z3[c * 2 + h];
        float coef = -0.5f * (1.0f / 64.0f) * p;  // -lam3 * p / HD
#pragma unroll
        for (int r = 0; r < 2; r++) {
            int hr = h * 2 + r;
            dqk[hr] = coef * d_tv3[m * 4 + hr];
            dtv[hr] = coef * d_qk3[m * 4 + hr];
        }
    }
#pragma unroll
    for (int hr = 0; hr < 4; hr++) {
        int off = hr * 64 + lane * 2;
        float2 qv  = *(const float2*)&d_P[(size_t)c * PW + 256 + off];
        float2 kuv = *(const float2*)&d_P[(size_t)u * PW + 512 + off];
        float2 kvv = *(const float2*)&d_P[(size_t)v * PW + 512 + off];
        float2 tvv = *(const float2*)&Tt[t * 256 + off];
        red2(&d_gP[(size_t)c * PW + 256 + off], dqk[hr] * kuv.x, dqk[hr] * kuv.y);
        red2(&d_gP[(size_t)u * PW + 512 + off], dqk[hr] * qv.x, dqk[hr] * qv.y);
        red2(&d_gP[(size_t)v * PW + 512 + off], dtv[hr] * tvv.x, dtv[hr] * tvv.y);
    }
}

// ---------------- LN backward + clip + step (warp per node) ----------------
__global__ __launch_bounds__(256) void finalize(const float* __restrict__ X,
                                                const float* __restrict__ gam,
                                                const float* __restrict__ stepp,
                                                float* __restrict__ out) {
    int w = threadIdx.x >> 5, lane = threadIdx.x & 31;
    int n = blockIdx.x * 8 + w;
    float4 x  = *(const float4*)&X[n * DD + lane * 4];
    float4 gg = *(const float4*)&d_gG[n * DD + lane * 4];
    float4 gm = *(const float4*)&gam[lane * 4];
    float mu = d_mu[n], rstd = d_rstd[n];
    float xh0 = (x.x - mu) * rstd, xh1 = (x.y - mu) * rstd, xh2 = (x.z - mu) * rstd, xh3 = (x.w - mu) * rstd;
    float gx0 = gg.x * gm.x, gx1 = gg.y * gm.y, gx2 = gg.z * gm.z, gx3 = gg.w * gm.w;
    float s1 = wsum(gx0 + gx1 + gx2 + gx3) * (1.0f / 128.0f);
    float s2v = wsum(gx0 * xh0 + gx1 * xh1 + gx2 * xh2 + gx3 * xh3) * (1.0f / 128.0f);
    float g0 = x.x + rstd * (gx0 - s1 - xh0 * s2v);
    float g1 = x.y + rstd * (gx1 - s1 - xh1 * s2v);
    float g2 = x.z + rstd * (gx2 - s1 - xh2 * s2v);
    float g3 = x.w + rstd * (gx3 - s1 - xh3 * s2v);
    float gn = sqrtf(wsum(g0 * g0 + g1 * g1 + g2 * g2 + g3 * g3));
    float sc = 1.0f / fmaxf(gn, 1.0f);            // GRAD_CLIP = 1
    float st = stepp[0] * sc;                      // DAMPING = 1
    float xn0 = x.x - st * g0, xn1 = x.y - st * g1, xn2 = x.z - st * g2, xn3 = x.w - st * g3;
    float sn = sqrtf(wsum(xn0 * xn0 + xn1 * xn1 + xn2 * xn2 + xn3 * xn3));
    float sc2 = 10.0f / fmaxf(sn, 10.0f);          // STATE_CLIP = 10
    float4 o = make_float4(xn0 * sc2, xn1 * sc2, xn2 * sc2, xn3 * sc2);
    *(float4*)&out[n * DD + lane * 4] = o;
}

__global__ void eg_copy(float* __restrict__ out) {
    int t = threadIdx.x;
    if (t < NG) out[NN * DD + t] = d_Eg[t];
}

// ---------------- host launch ----------------
extern "C" void kernel_launch(void* const* d_in, const int* in_sizes, int n_in,
                              void* d_out, int out_size) {
    const float* X     = (const float*)d_in[0];
    const int*   c2    = (const int*)d_in[1];
    const int*   u2    = (const int*)d_in[2];
    const int*   c3    = (const int*)d_in[3];
    const int*   u3    = (const int*)d_in[4];
    const int*   v3    = (const int*)d_in[5];
    const int*   tt    = (const int*)d_in[6];
    const int*   batch = (const int*)d_in[7];
    const float* a2    = (const float*)d_in[8];
    const float* step  = (const float*)d_in[9];
    const float* gam   = (const float*)d_in[10];
    const float* bet   = (const float*)d_in[11];
    const float* WQ2   = (const float*)d_in[12];
    const float* WK2   = (const float*)d_in[13];
    const float* WQ3   = (const float*)d_in[14];
    const float* WK3   = (const float*)d_in[15];
    const float* Tt    = (const float*)d_in[16];
    const float* WQm   = (const float*)d_in[17];
    const float* WKm   = (const float*)d_in[18];
    const float* Bm    = (const float*)d_in[19];
    float* out = (float*)d_out;

    static int smem_set = 0;
    if (!smem_set) {
        cudaFuncSetAttribute(gemm_mma<false>, cudaFuncAttributeMaxDynamicSharedMemorySize, 4 * TILEB);
        cudaFuncSetAttribute(gemm_mma<true>, cudaFuncAttributeMaxDynamicSharedMemorySize, 4 * TILEB);
        smem_set = 1;
    }

    void* p;
    cudaGetSymbolAddress(&p, d_gP); cudaMemsetAsync(p, 0, sizeof(float) * (size_t)NN * PW);
    cudaGetSymbolAddress(&p, d_z2); cudaMemsetAsync(p, 0, sizeof(float) * NN * 2);
    cudaGetSymbolAddress(&p, d_z3); cudaMemsetAsync(p, 0, sizeof(float) * NN * 2);
    cudaGetSymbolAddress(&p, d_Eg); cudaMemsetAsync(p, 0, sizeof(float) * NG);

    __nv_bfloat16 *pGh, *pGl, *pWh, *pWl, *pWTh, *pWTl;
    float *pP, *pgP, *pgG;
    cudaGetSymbolAddress((void**)&pGh, d_Gh);
    cudaGetSymbolAddress((void**)&pGl, d_Gl);
    cudaGetSymbolAddress((void**)&pWh, d_Wh);
    cudaGetSymbolAddress((void**)&pWl, d_Wl);
    cudaGetSymbolAddress((void**)&pWTh, d_WTh);
    cudaGetSymbolAddress((void**)&pWTl, d_WTl);
    cudaGetSymbolAddress((void**)&pP, d_P);
    cudaGetSymbolAddress((void**)&pgP, d_gP);
    cudaGetSymbolAddress((void**)&pgG, d_gG);

    ln_fwd<<<NN / 8, 256>>>(X, gam, bet);
    prep_wcat<<<(PW * DD + 255) / 256, 256>>>(WQ2, WK2, WQ3, WK3, WQm);
    km_kernel<<<1, 256>>>(Bm, WKm);
    // P = G @ Wcat^T  (fp32 out)
    gemm_mma<false><<<dim3(NN / 128, PW / 128), 256, 4 * TILEB>>>(
        pGh, pGl, DD, pWh, pWl, DD, pP, PW, DD);
    s2_fwd<<<EE / 8, 256>>>(c2, u2, a2);
    s3_fwd<<<MMOT / 8, 256>>>(c3, u3, v3, tt, Tt);
    node_energy<<<NN / 4, 128>>>(X, batch);
    pair_bwd<<<EE / 8, 256>>>(c2, u2);
    motif_bwd<<<MMOT / 8, 256>>>(c3, u3, v3, tt, Tt);
    // gG = gP @ Wcat  (A fp32 split in-flight; B = WT [n][k], K = 896)
    gemm_mma<true><<<dim3(NN / 128, 1), 256, 4 * TILEB>>>(
        pgP, nullptr, PW, pWTh, pWTl, PW, pgG, DD, PW);
    finalize<<<NN / 8, 256>>>(X, gam, step, out);
    eg_copy<<<1, 32>>>(out);
}

// round 14
// speedup vs baseline: 1.1031x; 1.1031x over previous
#include <cuda_runtime.h>
#include <cuda_bf16.h>
#include <math.h>
#include <stdint.h>

#define NN    32768
#define DD    128
#define EE    262144
#define MMOT  131072
#define NG    32
#define PW    896      // packed width: Q2[0:128) K2[128:256) Q3[256:512) K3[512:768) Qm[768:896)

// ---------------- scratch (device globals; no allocs allowed) ----------------
__device__ float          d_mu[NN];
__device__ float          d_rstd[NN];
__device__ __nv_bfloat16  d_Gh[NN * DD];
__device__ __nv_bfloat16  d_Gl[NN * DD];
__device__ __nv_bfloat16  d_Pb[NN * PW];    // bf16 projections
__device__ float          d_gP[NN * PW];    // fp32 gradient accumulator
__device__ __nv_bfloat16  d_gPh[NN * PW];
__device__ __nv_bfloat16  d_gPl[NN * PW];
__device__ float          d_gG[NN * DD];
__device__ __nv_bfloat16  d_Wh[PW * DD];    // [j][d]
__device__ __nv_bfloat16  d_Wl[PW * DD];
__device__ __nv_bfloat16  d_WTh[DD * PW];   // [d][j]
__device__ __nv_bfloat16  d_WTl[DD * PW];
__device__ float          d_Km[4096];       // [h][k][z] = [2][32][64]
__device__ float          d_w2[EE * 2];     // exp(s2)
__device__ float          d_w3[MMOT * 2];   // exp(s3)
__device__ float          d_qk3[MMOT * 4];
__device__ float          d_tv3[MMOT * 4];
__device__ float          d_z2[NN * 2];
__device__ float          d_z3[NN * 2];
__device__ float          d_Eg[NG];

// ---------------- helpers ----------------
__device__ __forceinline__ uint32_t smem_to_u32(const void* p) {
    uint32_t a;
    asm("{ .reg .u64 t; cvta.to.shared.u64 t, %1; cvt.u32.u64 %0, t; }" : "=r"(a) : "l"(p));
    return a;
}
__device__ __forceinline__ float wsum(float v) {
#pragma unroll
    for (int o = 16; o; o >>= 1) v += __shfl_xor_sync(0xffffffffu, v, o);
    return v;
}
__device__ __forceinline__ void red4(float* a, float x, float y, float z, float w) {
    asm volatile("red.global.add.v4.f32 [%0], {%1,%2,%3,%4};"
                 :: "l"(__cvta_generic_to_global(a)), "f"(x), "f"(y), "f"(z), "f"(w) : "memory");
}
__device__ __forceinline__ void red2(float* a, float x, float y) {
    asm volatile("red.global.add.v2.f32 [%0], {%1,%2};"
                 :: "l"(__cvta_generic_to_global(a)), "f"(x), "f"(y) : "memory");
}
__device__ __forceinline__ uint32_t pack_bf2(__nv_bfloat16 a, __nv_bfloat16 b) {
    __nv_bfloat162 p = __halves2bfloat162(a, b);
    return *(uint32_t*)&p;
}
__device__ __forceinline__ float4 ld_bf4(const __nv_bfloat16* p) {
    uint2 u = *(const uint2*)p;
    float2 fa = __bfloat1622float2(*(__nv_bfloat162*)&u.x);
    float2 fb = __bfloat1622float2(*(__nv_bfloat162*)&u.y);
    return make_float4(fa.x, fa.y, fb.x, fb.y);
}
__device__ __forceinline__ float2 ld_bf2(const __nv_bfloat16* p) {
    __nv_bfloat162 v = *(const __nv_bfloat162*)p;
    return __bfloat1622float2(v);
}
__device__ __forceinline__ void ldsm4(uint32_t* r, uint32_t addr) {
    asm volatile("ldmatrix.sync.aligned.m8n8.x4.shared.b16 {%0,%1,%2,%3}, [%4];"
                 : "=r"(r[0]), "=r"(r[1]), "=r"(r[2]), "=r"(r[3]) : "r"(addr));
}
__device__ __forceinline__ void mma16816(float* c, const uint32_t* a, const uint32_t* b) {
    asm volatile("mma.sync.aligned.m16n8k16.row.col.f32.bf16.bf16.f32 "
                 "{%0,%1,%2,%3}, {%4,%5,%6,%7}, {%8,%9}, {%0,%1,%2,%3};"
                 : "+f"(c[0]), "+f"(c[1]), "+f"(c[2]), "+f"(c[3])
                 : "r"(a[0]), "r"(a[1]), "r"(a[2]), "r"(a[3]), "r"(b[0]), "r"(b[1]));
}

// ---------------- layernorm forward -> G split into bf16 hi/lo ----------------
__global__ __launch_bounds__(256) void ln_fwd(const float* __restrict__ X,
                                              const float* __restrict__ gam,
                                              const float* __restrict__ bet) {
    int w = threadIdx.x >> 5, lane = threadIdx.x & 31;
    int n = blockIdx.x * 8 + w;
    float4 x = *(const float4*)&X[n * DD + lane * 4];
    float mu = wsum(x.x + x.y + x.z + x.w) * (1.0f / 128.0f);
    float dx0 = x.x - mu, dx1 = x.y - mu, dx2 = x.z - mu, dx3 = x.w - mu;
    float v = wsum(dx0 * dx0 + dx1 * dx1 + dx2 * dx2 + dx3 * dx3) * (1.0f / 128.0f);
    float rstd = rsqrtf(v + 1e-5f);
    float4 g = *(const float4*)&gam[lane * 4];
    float4 b = *(const float4*)&bet[lane * 4];
    float o0 = g.x * dx0 * rstd + b.x;
    float o1 = g.y * dx1 * rstd + b.y;
    float o2 = g.z * dx2 * rstd + b.z;
    float o3 = g.w * dx3 * rstd + b.w;
    __nv_bfloat16 h0 = __float2bfloat16(o0), h1 = __float2bfloat16(o1);
    __nv_bfloat16 h2 = __float2bfloat16(o2), h3 = __float2bfloat16(o3);
    __nv_bfloat16 l0 = __float2bfloat16(o0 - __bfloat162float(h0));
    __nv_bfloat16 l1 = __float2bfloat16(o1 - __bfloat162float(h1));
    __nv_bfloat16 l2 = __float2bfloat16(o2 - __bfloat162float(h2));
    __nv_bfloat16 l3 = __float2bfloat16(o3 - __bfloat162float(h3));
    *(uint2*)&d_Gh[n * DD + lane * 4] = make_uint2(pack_bf2(h0, h1), pack_bf2(h2, h3));
    *(uint2*)&d_Gl[n * DD + lane * 4] = make_uint2(pack_bf2(l0, l1), pack_bf2(l2, l3));
    if (lane == 0) { d_mu[n] = mu; d_rstd[n] = rstd; }
}

// ---------------- pack weights (hi/lo bf16, direct + transposed) ----------------
__global__ void prep_wcat(const float* __restrict__ WQ2, const float* __restrict__ WK2,
                          const float* __restrict__ WQ3, const float* __restrict__ WK3,
                          const float* __restrict__ WQm) {
    int i = blockIdx.x * 256 + threadIdx.x;
    if (i >= PW * DD) return;
    int j = i >> 7, d = i & 127;
    float v;
    if (j < 128)      v = WQ2[j * 128 + d];
    else if (j < 256) v = WK2[(j - 128) * 128 + d];
    else if (j < 512) v = WQ3[(j - 256) * 128 + d];
    else if (j < 768) v = WK3[(j - 512) * 128 + d];
    else              v = WQm[(j - 768) * 128 + d];
    __nv_bfloat16 h = __float2bfloat16(v);
    __nv_bfloat16 l = __float2bfloat16(v - __bfloat162float(h));
    d_Wh[i] = h; d_Wl[i] = l;
    d_WTh[d * PW + j] = h; d_WTl[d * PW + j] = l;
}

// ---------------- split gP into bf16 hi/lo ----------------
__global__ __launch_bounds__(256) void gp_conv() {
    int i = (blockIdx.x * 256 + threadIdx.x) * 4;
    float4 v = *(const float4*)&d_gP[i];
    __nv_bfloat16 h0 = __float2bfloat16(v.x), h1 = __float2bfloat16(v.y);
    __nv_bfloat16 h2 = __float2bfloat16(v.z), h3 = __float2bfloat16(v.w);
    __nv_bfloat16 l0 = __float2bfloat16(v.x - __bfloat162float(h0));
    __nv_bfloat16 l1 = __float2bfloat16(v.y - __bfloat162float(h1));
    __nv_bfloat16 l2 = __float2bfloat16(v.z - __bfloat162float(h2));
    __nv_bfloat16 l3 = __float2bfloat16(v.w - __bfloat162float(h3));
    *(uint2*)&d_gPh[i] = make_uint2(pack_bf2(h0, h1), pack_bf2(h2, h3));
    *(uint2*)&d_gPl[i] = make_uint2(pack_bf2(l0, l1), pack_bf2(l2, l3));
}

// ---------------- Km = B_mem @ W_Km^T : [2][32][64] ----------------
__global__ void km_kernel(const float* __restrict__ Bm, const float* __restrict__ WKm) {
    for (int i = threadIdx.x; i < 4096; i += 256) {
        int h = i >> 11, k = (i >> 6) & 31, z = i & 63;
        const float* brow = &Bm[k * 128];
        const float* wrow = &WKm[(h * 64 + z) * 128];
        float acc = 0.f;
#pragma unroll
        for (int dd = 0; dd < 128; dd += 4) {
            float4 b4 = *(const float4*)&brow[dd];
            float4 w4 = *(const float4*)&wrow[dd];
            acc += b4.x * w4.x + b4.y * w4.y + b4.z * w4.z + b4.w * w4.w;
        }
        d_Km[i] = acc;
    }
}

// ---------------- mma.sync GEMM core: C[128,128] tile = A[128,K] @ B[128,K]^T ----------------
// bf16 split precision: C = Ah@Bh^T + Ah@Bl^T + Al@Bh^T, fp32 accumulate.
// smem tiles [128][72] bf16 (row stride 144B); K chunked by 64.
#define TILEB 18432   // 128 * 72 * 2

__device__ __forceinline__ void ld_tile64(const __nv_bfloat16* __restrict__ src, int ld,
                                          char* dst, int tid) {
#pragma unroll
    for (int it = 0; it < 4; it++) {
        int c = it * 256 + tid;            // 1024 chunks of 16B
        int r = c >> 3, c8 = (c & 7) << 3; // row, bf16 col
        *(uint4*)(dst + r * 144 + (c8 << 1)) = *(const uint4*)&src[(size_t)r * ld + c8];
    }
}

__device__ __forceinline__ void gemm_core(
    const __nv_bfloat16* __restrict__ Ah, const __nv_bfloat16* __restrict__ Al, int lda,
    const __nv_bfloat16* __restrict__ Bh, const __nv_bfloat16* __restrict__ Bl, int ldb,
    int Kdim, char* smem, uint32_t sb, int tid, int wid, int lane,
    int wm, int wn, float acc[4][4][4])
{
    uint32_t aoff[4], boff[2];
#pragma unroll
    for (int mt = 0; mt < 4; mt++)
        aoff[mt] = (uint32_t)((wm + mt * 16 + (lane & 15)) * 144 + ((lane >> 4) << 4));
#pragma unroll
    for (int p = 0; p < 2; p++)
        boff[p] = (uint32_t)((wn + p * 16 + ((lane >> 4) << 3) + (lane & 7)) * 144 +
                             (((lane >> 3) & 1) << 4));

    for (int kc = 0; kc < Kdim; kc += 64) {
        ld_tile64(Ah + kc, lda, smem + 0 * TILEB, tid);
        ld_tile64(Al + kc, lda, smem + 1 * TILEB, tid);
        ld_tile64(Bh + kc, ldb, smem + 2 * TILEB, tid);
        ld_tile64(Bl + kc, ldb, smem + 3 * TILEB, tid);
        __syncthreads();
#pragma unroll
        for (int ks = 0; ks < 4; ks++) {
            uint32_t ksb = ks * 32;  // 16 bf16 = 32 bytes
            uint32_t ah[4][4], al[4][4], bh[4][2], bl[4][2];
#pragma unroll
            for (int mt = 0; mt < 4; mt++) ldsm4(ah[mt], sb + 0 * TILEB + aoff[mt] + ksb);
#pragma unroll
            for (int p = 0; p < 2; p++) {
                uint32_t r4[4];
                ldsm4(r4, sb + 2 * TILEB + boff[p] + ksb);
                bh[2 * p][0] = r4[0]; bh[2 * p][1] = r4[1];
                bh[2 * p + 1][0] = r4[2]; bh[2 * p + 1][1] = r4[3];
            }
#pragma unroll
            for (int mt = 0; mt < 4; mt++)
#pragma unroll
                for (int nt = 0; nt < 4; nt++) mma16816(acc[mt][nt], ah[mt], bh[nt]);
#pragma unroll
            for (int p = 0; p < 2; p++) {
                uint32_t r4[4];
                ldsm4(r4, sb + 3 * TILEB + boff[p] + ksb);
                bl[2 * p][0] = r4[0]; bl[2 * p][1] = r4[1];
                bl[2 * p + 1][0] = r4[2]; bl[2 * p + 1][1] = r4[3];
            }
#pragma unroll
            for (int mt = 0; mt < 4; mt++)
#pragma unroll
                for (int nt = 0; nt < 4; nt++) mma16816(acc[mt][nt], ah[mt], bl[nt]);
#pragma unroll
            for (int mt = 0; mt < 4; mt++) ldsm4(al[mt], sb + 1 * TILEB + aoff[mt] + ksb);
#pragma unroll
            for (int mt = 0; mt < 4; mt++)
#pragma unroll
                for (int nt = 0; nt < 4; nt++) mma16816(acc[mt][nt], al[mt], bh[nt]);
        }
        __syncthreads();
    }
}

// FWD: Pb[N,896] (bf16) = G @ Wcat^T
__global__ __launch_bounds__(256, 2) void gemm_fwd() {
    extern __shared__ __align__(16) char smem[];
    int tid = threadIdx.x, wid = tid >> 5, lane = tid & 31;
    int row0 = blockIdx.x * 128, col0 = blockIdx.y * 128;
    int wm = (wid & 1) * 64, wn = (wid >> 1) * 32;
    float acc[4][4][4];
#pragma unroll
    for (int i = 0; i < 4; i++)
#pragma unroll
        for (int j = 0; j < 4; j++)
#pragma unroll
            for (int k = 0; k < 4; k++) acc[i][j][k] = 0.f;
    gemm_core(d_Gh + (size_t)row0 * DD, d_Gl + (size_t)row0 * DD, DD,
              d_Wh + (size_t)col0 * DD, d_Wl + (size_t)col0 * DD, DD,
              DD, smem, smem_to_u32(smem), tid, wid, lane, wm, wn, acc);
    int g = lane >> 2, tg = lane & 3;
#pragma unroll
    for (int mt = 0; mt < 4; mt++) {
        int r = row0 + wm + mt * 16 + g;
#pragma unroll
        for (int nt = 0; nt < 4; nt++) {
            int cg = col0 + wn + nt * 8 + tg * 2;
            *(__nv_bfloat162*)&d_Pb[(size_t)r * PW + cg] =
                __floats2bfloat162_rn(acc[mt][nt][0], acc[mt][nt][1]);
            *(__nv_bfloat162*)&d_Pb[(size_t)(r + 8) * PW + cg] =
                __floats2bfloat162_rn(acc[mt][nt][2], acc[mt][nt][3]);
        }
    }
}

// BWD: gG[N,128] (fp32) = gP @ Wcat (presplit gPh/gPl; B = WT)
__global__ __launch_bounds__(256, 2) void gemm_bwd() {
    extern __shared__ __align__(16) char smem[];
    int tid = threadIdx.x, wid = tid >> 5, lane = tid & 31;
    int row0 = blockIdx.x * 128;
    int wm = (wid & 1) * 64, wn = (wid >> 1) * 32;
    float acc[4][4][4];
#pragma unroll
    for (int i = 0; i < 4; i++)
#pragma unroll
        for (int j = 0; j < 4; j++)
#pragma unroll
            for (int k = 0; k < 4; k++) acc[i][j][k] = 0.f;
    gemm_core(d_gPh + (size_t)row0 * PW, d_gPl + (size_t)row0 * PW, PW,
              d_WTh, d_WTl, PW,
              PW, smem, smem_to_u32(smem), tid, wid, lane, wm, wn, acc);
    int g = lane >> 2, tg = lane & 3;
#pragma unroll
    for (int mt = 0; mt < 4; mt++) {
        int r = row0 + wm + mt * 16 + g;
#pragma unroll
        for (int nt = 0; nt < 4; nt++) {
            int cg = wn + nt * 8 + tg * 2;
            *(float2*)&d_gG[(size_t)r * DD + cg] = make_float2(acc[mt][nt][0], acc[mt][nt][1]);
            *(float2*)&d_gG[(size_t)(r + 8) * DD + cg] = make_float2(acc[mt][nt][2], acc[mt][nt][3]);
        }
    }
}

// ---------------- pair forward: w2 = exp(s2), z2 += w2 (warp per edge) ----------------
__global__ __launch_bounds__(256) void s2_fwd(const int* __restrict__ c2, const int* __restrict__ u2,
                                              const float* __restrict__ a2) {
    int e = blockIdx.x * 8 + (threadIdx.x >> 5);
    int lane = threadIdx.x & 31;
    int c = c2[e], u = u2[e];
    float4 q = ld_bf4(&d_Pb[(size_t)c * PW + lane * 4]);
    float4 k = ld_bf4(&d_Pb[(size_t)u * PW + 128 + lane * 4]);
    float p = q.x * k.x + q.y * k.y + q.z * k.z + q.w * k.w;
    p += __shfl_down_sync(0xffffffffu, p, 8);
    p += __shfl_down_sync(0xffffffffu, p, 4);
    p += __shfl_down_sync(0xffffffffu, p, 2);
    p += __shfl_down_sync(0xffffffffu, p, 1);
    if ((lane & 15) == 0) {
        int h = lane >> 4;
        float s = p * 0.125f + a2[e * 2 + h];
        float w = __expf(s);
        d_w2[e * 2 + h] = w;
        atomicAdd(&d_z2[c * 2 + h], w);
    }
}

// ---------------- motif forward (warp per motif) ----------------
__global__ __launch_bounds__(256) void s3_fwd(const int* __restrict__ c3, const int* __restrict__ u3,
                                              const int* __restrict__ v3, const int* __restrict__ tt,
                                              const float* __restrict__ Tt) {
    int m = blockIdx.x * 8 + (threadIdx.x >> 5);
    int lane = threadIdx.x & 31;
    int c = c3[m], u = u3[m], v = v3[m], t = tt[m];
    const __nv_bfloat16* Q  = &d_Pb[(size_t)c * PW + 256];
    const __nv_bfloat16* KU = &d_Pb[(size_t)u * PW + 512];
    const __nv_bfloat16* KV = &d_Pb[(size_t)v * PW + 512];
    const float* T  = &Tt[t * 256];
    float qk[4], tv[4];
#pragma unroll
    for (int hr = 0; hr < 4; hr++) {
        int off = hr * 64 + lane * 2;
        float2 qv  = ld_bf2(&Q[off]);
        float2 kuv = ld_bf2(&KU[off]);
        float2 kvv = ld_bf2(&KV[off]);
        float2 tvv = *(const float2*)&T[off];
        qk[hr] = qv.x * kuv.x + qv.y * kuv.y;
        tv[hr] = tvv.x * kvv.x + tvv.y * kvv.y;
    }
#pragma unroll
    for (int hr = 0; hr < 4; hr++) { qk[hr] = wsum(qk[hr]); tv[hr] = wsum(tv[hr]); }
    if (lane == 0) {
#pragma unroll
        for (int hr = 0; hr < 4; hr++) { d_qk3[m * 4 + hr] = qk[hr]; d_tv3[m * 4 + hr] = tv[hr]; }
#pragma unroll
        for (int h = 0; h < 2; h++) {
            float s = (qk[h * 2] * tv[h * 2] + qk[h * 2 + 1] * tv[h * 2 + 1]) * (1.0f / 64.0f);
            float w = __expf(s);
            d_w3[m * 2 + h] = w;
            atomicAdd(&d_z3[c * 2 + h], w);
        }
    }
}

// ---------------- per-node: memory term (fwd+bwd) + energies -> Eg ----------------
__global__ __launch_bounds__(128) void node_energy(const float* __restrict__ X,
                                                   const int* __restrict__ batch) {
    __shared__ float sKm[2 * 32 * 65];
    __shared__ float sQm[4][128];
    __shared__ float sPm[4][2][32];
    int tid = threadIdx.x;
    int w = tid >> 5, lane = tid & 31;
    for (int i = tid; i < 4096; i += 128) {
        int h = i >> 11, k = (i >> 6) & 31, z = i & 63;
        sKm[(h * 32 + k) * 65 + z] = d_Km[i];
    }
    __syncthreads();
    int n = blockIdx.x * 4 + w;
    *(float4*)&sQm[w][lane * 4] = ld_bf4(&d_Pb[(size_t)n * PW + 768 + lane * 4]);
    __syncwarp();
    float smv[2];
#pragma unroll
    for (int h = 0; h < 2; h++) {
        const float* kmrow = &sKm[(h * 32 + lane) * 65];
        const float* qrow = &sQm[w][h * 64];
        float acc = 0.f;
#pragma unroll
        for (int z = 0; z < 64; z++) acc += qrow[z] * kmrow[z];
        smv[h] = acc * 0.125f;
    }
    float e_mem = 0.f;
#pragma unroll
    for (int h = 0; h < 2; h++) {
        float mx = smv[h];
#pragma unroll
        for (int o = 16; o; o >>= 1) mx = fmaxf(mx, __shfl_xor_sync(0xffffffffu, mx, o));
        float ex = __expf(smv[h] - mx);
        float zs = wsum(ex);
        e_mem -= (mx + logf(zs));          // lamm = bm = 1
        sPm[w][h][lane] = ex / zs;
    }
    __syncwarp();
#pragma unroll
    for (int h = 0; h < 2; h++)
#pragma unroll
        for (int t2 = 0; t2 < 2; t2++) {
            int z = lane + 32 * t2;
            float g = 0.f;
#pragma unroll
            for (int k = 0; k < 32; k++) g += sPm[w][h][k] * sKm[(h * 32 + k) * 65 + z];
            d_gP[(size_t)n * PW + 768 + h * 64 + z] = -0.125f * g;
        }
    float4 xv = *(const float4*)&X[n * DD + lane * 4];
    float xs = wsum(xv.x * xv.x + xv.y * xv.y + xv.z * xv.z + xv.w * xv.w);
    if (lane == 0) {
        float e = 0.5f * xs + e_mem;
#pragma unroll
        for (int h = 0; h < 2; h++) {
            float z2v = d_z2[n * 2 + h];
            if (z2v > 0.f) e -= logf(z2v);            // lam2 = 1
            float z3v = d_z3[n * 2 + h];
            if (z3v > 0.f) e -= 0.5f * logf(z3v);     // lam3 = 0.5
        }
        atomicAdd(&d_Eg[batch[n]], e);
    }
}

// ---------------- pair backward (warp per edge) ----------------
__global__ __launch_bounds__(256) void pair_bwd(const int* __restrict__ c2, const int* __restrict__ u2) {
    int e = blockIdx.x * 8 + (threadIdx.x >> 5);
    int lane = threadIdx.x & 31;
    int c = c2[e], u = u2[e];
    int h = lane >> 4;
    float p = d_w2[e * 2 + h] / d_z2[c * 2 + h];
    float cf = -0.125f * p;                       // -lam2 * p / sqrt(HD)
    float4 q = ld_bf4(&d_Pb[(size_t)c * PW + lane * 4]);
    float4 k = ld_bf4(&d_Pb[(size_t)u * PW + 128 + lane * 4]);
    red4(&d_gP[(size_t)c * PW + lane * 4], cf * k.x, cf * k.y, cf * k.z, cf * k.w);
    red4(&d_gP[(size_t)u * PW + 128 + lane * 4], cf * q.x, cf * q.y, cf * q.z, cf * q.w);
}

// ---------------- motif backward (warp per motif) ----------------
__global__ __launch_bounds__(256) void motif_bwd(const int* __restrict__ c3, const int* __restrict__ u3,
                                                 const int* __restrict__ v3, const int* __restrict__ tt,
                                                 const float* __restrict__ Tt) {
    int m = blockIdx.x * 8 + (threadIdx.x >> 5);
    int lane = threadIdx.x & 31;
    int c = c3[m], u = u3[m], v = v3[m], t = tt[m];
    float dqk[4], dtv[4];
#pragma unroll
    for (int h = 0; h < 2; h++) {
        float p = d_w3[m * 2 + h] / d_z3[c * 2 + h];
        float coef = -0.5f * (1.0f / 64.0f) * p;  // -lam3 * p / HD
#pragma unroll
        for (int r = 0; r < 2; r++) {
            int hr = h * 2 + r;
            dqk[hr] = coef * d_tv3[m * 4 + hr];
            dtv[hr] = coef * d_qk3[m * 4 + hr];
        }
    }
#pragma unroll
    for (int hr = 0; hr < 4; hr++) {
        int off = hr * 64 + lane * 2;
        float2 qv  = ld_bf2(&d_Pb[(size_t)c * PW + 256 + off]);
        float2 kuv = ld_bf2(&d_Pb[(size_t)u * PW + 512 + off]);
        float2 kvv = ld_bf2(&d_Pb[(size_t)v * PW + 512 + off]);
        float2 tvv = *(const float2*)&Tt[t * 256 + off];
        red2(&d_gP[(size_t)c * PW + 256 + off], dqk[hr] * kuv.x, dqk[hr] * kuv.y);
        red2(&d_gP[(size_t)u * PW + 512 + off], dqk[hr] * qv.x, dqk[hr] * qv.y);
        red2(&d_gP[(size_t)v * PW + 512 + off], dtv[hr] * tvv.x, dtv[hr] * tvv.y);
    }
}

// ---------------- LN backward + clip + step (warp per node) ----------------
__global__ __launch_bounds__(256) void finalize(const float* __restrict__ X,
                                                const float* __restrict__ gam,
                                                const float* __restrict__ stepp,
                                                float* __restrict__ out) {
    int w = threadIdx.x >> 5, lane = threadIdx.x & 31;
    int n = blockIdx.x * 8 + w;
    float4 x  = *(const float4*)&X[n * DD + lane * 4];
    float4 gg = *(const float4*)&d_gG[n * DD + lane * 4];
    float4 gm = *(const float4*)&gam[lane * 4];
    float mu = d_mu[n], rstd = d_rstd[n];
    float xh0 = (x.x - mu) * rstd, xh1 = (x.y - mu) * rstd, xh2 = (x.z - mu) * rstd, xh3 = (x.w - mu) * rstd;
    float gx0 = gg.x * gm.x, gx1 = gg.y * gm.y, gx2 = gg.z * gm.z, gx3 = gg.w * gm.w;
    float s1 = wsum(gx0 + gx1 + gx2 + gx3) * (1.0f / 128.0f);
    float s2v = wsum(gx0 * xh0 + gx1 * xh1 + gx2 * xh2 + gx3 * xh3) * (1.0f / 128.0f);
    float g0 = x.x + rstd * (gx0 - s1 - xh0 * s2v);
    float g1 = x.y + rstd * (gx1 - s1 - xh1 * s2v);
    float g2 = x.z + rstd * (gx2 - s1 - xh2 * s2v);
    float g3 = x.w + rstd * (gx3 - s1 - xh3 * s2v);
    float gn = sqrtf(wsum(g0 * g0 + g1 * g1 + g2 * g2 + g3 * g3));
    float sc = 1.0f / fmaxf(gn, 1.0f);            // GRAD_CLIP = 1
    float st = stepp[0] * sc;                      // DAMPING = 1
    float xn0 = x.x - st * g0, xn1 = x.y - st * g1, xn2 = x.z - st * g2, xn3 = x.w - st * g3;
    float sn = sqrtf(wsum(xn0 * xn0 + xn1 * xn1 + xn2 * xn2 + xn3 * xn3));
    float sc2 = 10.0f / fmaxf(sn, 10.0f);          // STATE_CLIP = 10
    float4 o = make_float4(xn0 * sc2, xn1 * sc2, xn2 * sc2, xn3 * sc2);
    *(float4*)&out[n * DD + lane * 4] = o;
}

__global__ void eg_copy(float* __restrict__ out) {
    int t = threadIdx.x;
    if (t < NG) out[NN * DD + t] = d_Eg[t];
}

// ---------------- host launch ----------------
extern "C" void kernel_launch(void* const* d_in, const int* in_sizes, int n_in,
                              void* d_out, int out_size) {
    const float* X     = (const float*)d_in[0];
    const int*   c2    = (const int*)d_in[1];
    const int*   u2    = (const int*)d_in[2];
    const int*   c3    = (const int*)d_in[3];
    const int*   u3    = (const int*)d_in[4];
    const int*   v3    = (const int*)d_in[5];
    const int*   tt    = (const int*)d_in[6];
    const int*   batch = (const int*)d_in[7];
    const float* a2    = (const float*)d_in[8];
    const float* step  = (const float*)d_in[9];
    const float* gam   = (const float*)d_in[10];
    const float* bet   = (const float*)d_in[11];
    const float* WQ2   = (const float*)d_in[12];
    const float* WK2   = (const float*)d_in[13];
    const float* WQ3   = (const float*)d_in[14];
    const float* WK3   = (const float*)d_in[15];
    const float* Tt    = (const float*)d_in[16];
    const float* WQm   = (const float*)d_in[17];
    const float* WKm   = (const float*)d_in[18];
    const float* Bm    = (const float*)d_in[19];
    float* out = (float*)d_out;

    static int smem_set = 0;
    if (!smem_set) {
        cudaFuncSetAttribute(gemm_fwd, cudaFuncAttributeMaxDynamicSharedMemorySize, 4 * TILEB);
        cudaFuncSetAttribute(gemm_bwd, cudaFuncAttributeMaxDynamicSharedMemorySize, 4 * TILEB);
        smem_set = 1;
    }

    void* p;
    cudaGetSymbolAddress(&p, d_gP); cudaMemsetAsync(p, 0, sizeof(float) * (size_t)NN * PW);
    cudaGetSymbolAddress(&p, d_z2); cudaMemsetAsync(p, 0, sizeof(float) * NN * 2);
    cudaGetSymbolAddress(&p, d_z3); cudaMemsetAsync(p, 0, sizeof(float) * NN * 2);
    cudaGetSymbolAddress(&p, d_Eg); cudaMemsetAsync(p, 0, sizeof(float) * NG);

    ln_fwd<<<NN / 8, 256>>>(X, gam, bet);
    prep_wcat<<<(PW * DD + 255) / 256, 256>>>(WQ2, WK2, WQ3, WK3, WQm);
    km_kernel<<<1, 256>>>(Bm, WKm);
    // Pb = bf16(G @ Wcat^T)
    gemm_fwd<<<dim3(NN / 128, PW / 128), 256, 4 * TILEB>>>();
    s2_fwd<<<EE / 8, 256>>>(c2, u2, a2);
    s3_fwd<<<MMOT / 8, 256>>>(c3, u3, v3, tt, Tt);
    node_energy<<<NN / 4, 128>>>(X, batch);
    pair_bwd<<<EE / 8, 256>>>(c2, u2);
    motif_bwd<<<MMOT / 8, 256>>>(c3, u3, v3, tt, Tt);
    gp_conv<<<(NN * PW) / 1024, 256>>>();
    // gG = gP @ Wcat  (presplit bf16; B = WT)
    gemm_bwd<<<dim3(NN / 128, 1), 256, 4 * TILEB>>>();
    finalize<<<NN / 8, 256>>>(X, gam, step, out);
    eg_copy<<<1, 32>>>(out);
}

// round 15
// speedup vs baseline: 1.1105x; 1.0067x over previous
#include <cuda_runtime.h>
#include <cuda_bf16.h>
#include <math.h>
#include <stdint.h>

#define NN    32768
#define DD    128
#define EE    262144
#define MMOT  131072
#define NG    32
#define PW    896      // packed width: Q2[0:128) K2[128:256) Q3[256:512) K3[512:768) Qm[768:896)

// ---------------- scratch (device globals; no allocs allowed) ----------------
__device__ float          d_mu[NN];
__device__ float          d_rstd[NN];
__device__ float          d_en[NN];         // per-node partial energy
__device__ __nv_bfloat16  d_Gh[NN * DD];
__device__ __nv_bfloat16  d_Gl[NN * DD];
__device__ __nv_bfloat16  d_Pb[NN * PW];    // bf16 projections
__device__ float          d_gP[NN * PW];    // fp32 gradient accumulator
__device__ __nv_bfloat16  d_gPh[NN * PW];
__device__ __nv_bfloat16  d_gPl[NN * PW];
__device__ float          d_gG[NN * DD];
__device__ __nv_bfloat16  d_Wh[PW * DD];    // [j][d]
__device__ __nv_bfloat16  d_Wl[PW * DD];
__device__ __nv_bfloat16  d_WTh[DD * PW];   // [d][j]
__device__ __nv_bfloat16  d_WTl[DD * PW];
__device__ float          d_Km[4096];       // [h][k][z] = [2][32][64]
__device__ float          d_w2[EE * 2];     // exp(s2)
__device__ float          d_w3[MMOT * 2];   // exp(s3)
__device__ float          d_qk3[MMOT * 4];
__device__ float          d_tv3[MMOT * 4];
__device__ float          d_z2[NN * 2];
__device__ float          d_z3[NN * 2];
__device__ float          d_Eg[NG];

// ---------------- helpers ----------------
__device__ __forceinline__ uint32_t smem_to_u32(const void* p) {
    uint32_t a;
    asm("{ .reg .u64 t; cvta.to.shared.u64 t, %1; cvt.u32.u64 %0, t; }" : "=r"(a) : "l"(p));
    return a;
}
__device__ __forceinline__ float wsum(float v) {
#pragma unroll
    for (int o = 16; o; o >>= 1) v += __shfl_xor_sync(0xffffffffu, v, o);
    return v;
}
__device__ __forceinline__ void red4(float* a, float x, float y, float z, float w) {
    asm volatile("red.global.add.v4.f32 [%0], {%1,%2,%3,%4};"
                 :: "l"(__cvta_generic_to_global(a)), "f"(x), "f"(y), "f"(z), "f"(w) : "memory");
}
__device__ __forceinline__ void red2(float* a, float x, float y) {
    asm volatile("red.global.add.v2.f32 [%0], {%1,%2};"
                 :: "l"(__cvta_generic_to_global(a)), "f"(x), "f"(y) : "memory");
}
__device__ __forceinline__ uint32_t pack_bf2(__nv_bfloat16 a, __nv_bfloat16 b) {
    __nv_bfloat162 p = __halves2bfloat162(a, b);
    return *(uint32_t*)&p;
}
__device__ __forceinline__ float4 ld_bf4(const __nv_bfloat16* p) {
    uint2 u = *(const uint2*)p;
    float2 fa = __bfloat1622float2(*(__nv_bfloat162*)&u.x);
    float2 fb = __bfloat1622float2(*(__nv_bfloat162*)&u.y);
    return make_float4(fa.x, fa.y, fb.x, fb.y);
}
__device__ __forceinline__ float2 ld_bf2(const __nv_bfloat16* p) {
    __nv_bfloat162 v = *(const __nv_bfloat162*)p;
    return __bfloat1622float2(v);
}
__device__ __forceinline__ void ldsm4(uint32_t* r, uint32_t addr) {
    asm volatile("ldmatrix.sync.aligned.m8n8.x4.shared.b16 {%0,%1,%2,%3}, [%4];"
                 : "=r"(r[0]), "=r"(r[1]), "=r"(r[2]), "=r"(r[3]) : "r"(addr));
}
__device__ __forceinline__ void mma16816(float* c, const uint32_t* a, const uint32_t* b) {
    asm volatile("mma.sync.aligned.m16n8k16.row.col.f32.bf16.bf16.f32 "
                 "{%0,%1,%2,%3}, {%4,%5,%6,%7}, {%8,%9}, {%0,%1,%2,%3};"
                 : "+f"(c[0]), "+f"(c[1]), "+f"(c[2]), "+f"(c[3])
                 : "r"(a[0]), "r"(a[1]), "r"(a[2]), "r"(a[3]), "r"(b[0]), "r"(b[1]));
}

// ---------------- layernorm forward -> G split into bf16 hi/lo ----------------
__global__ __launch_bounds__(256) void ln_fwd(const float* __restrict__ X,
                                              const float* __restrict__ gam,
                                              const float* __restrict__ bet) {
    int w = threadIdx.x >> 5, lane = threadIdx.x & 31;
    int n = blockIdx.x * 8 + w;
    float4 x = *(const float4*)&X[n * DD + lane * 4];
    float mu = wsum(x.x + x.y + x.z + x.w) * (1.0f / 128.0f);
    float dx0 = x.x - mu, dx1 = x.y - mu, dx2 = x.z - mu, dx3 = x.w - mu;
    float v = wsum(dx0 * dx0 + dx1 * dx1 + dx2 * dx2 + dx3 * dx3) * (1.0f / 128.0f);
    float rstd = rsqrtf(v + 1e-5f);
    float4 g = *(const float4*)&gam[lane * 4];
    float4 b = *(const float4*)&bet[lane * 4];
    float o0 = g.x * dx0 * rstd + b.x;
    float o1 = g.y * dx1 * rstd + b.y;
    float o2 = g.z * dx2 * rstd + b.z;
    float o3 = g.w * dx3 * rstd + b.w;
    __nv_bfloat16 h0 = __float2bfloat16(o0), h1 = __float2bfloat16(o1);
    __nv_bfloat16 h2 = __float2bfloat16(o2), h3 = __float2bfloat16(o3);
    __nv_bfloat16 l0 = __float2bfloat16(o0 - __bfloat162float(h0));
    __nv_bfloat16 l1 = __float2bfloat16(o1 - __bfloat162float(h1));
    __nv_bfloat16 l2 = __float2bfloat16(o2 - __bfloat162float(h2));
    __nv_bfloat16 l3 = __float2bfloat16(o3 - __bfloat162float(h3));
    *(uint2*)&d_Gh[n * DD + lane * 4] = make_uint2(pack_bf2(h0, h1), pack_bf2(h2, h3));
    *(uint2*)&d_Gl[n * DD + lane * 4] = make_uint2(pack_bf2(l0, l1), pack_bf2(l2, l3));
    if (lane == 0) { d_mu[n] = mu; d_rstd[n] = rstd; }
}

// ---------------- pack weights (hi/lo bf16, direct + transposed) ----------------
__global__ void prep_wcat(const float* __restrict__ WQ2, const float* __restrict__ WK2,
                          const float* __restrict__ WQ3, const float* __restrict__ WK3,
                          const float* __restrict__ WQm) {
    int i = blockIdx.x * 256 + threadIdx.x;
    if (i >= PW * DD) return;
    int j = i >> 7, d = i & 127;
    float v;
    if (j < 128)      v = WQ2[j * 128 + d];
    else if (j < 256) v = WK2[(j - 128) * 128 + d];
    else if (j < 512) v = WQ3[(j - 256) * 128 + d];
    else if (j < 768) v = WK3[(j - 512) * 128 + d];
    else              v = WQm[(j - 768) * 128 + d];
    __nv_bfloat16 h = __float2bfloat16(v);
    __nv_bfloat16 l = __float2bfloat16(v - __bfloat162float(h));
    d_Wh[i] = h; d_Wl[i] = l;
    d_WTh[d * PW + j] = h; d_WTl[d * PW + j] = l;
}

// ---------------- split gP into bf16 hi/lo ----------------
__global__ __launch_bounds__(256) void gp_conv() {
    int i = (blockIdx.x * 256 + threadIdx.x) * 4;
    float4 v = *(const float4*)&d_gP[i];
    __nv_bfloat16 h0 = __float2bfloat16(v.x), h1 = __float2bfloat16(v.y);
    __nv_bfloat16 h2 = __float2bfloat16(v.z), h3 = __float2bfloat16(v.w);
    __nv_bfloat16 l0 = __float2bfloat16(v.x - __bfloat162float(h0));
    __nv_bfloat16 l1 = __float2bfloat16(v.y - __bfloat162float(h1));
    __nv_bfloat16 l2 = __float2bfloat16(v.z - __bfloat162float(h2));
    __nv_bfloat16 l3 = __float2bfloat16(v.w - __bfloat162float(h3));
    *(uint2*)&d_gPh[i] = make_uint2(pack_bf2(h0, h1), pack_bf2(h2, h3));
    *(uint2*)&d_gPl[i] = make_uint2(pack_bf2(l0, l1), pack_bf2(l2, l3));
}

// ---------------- Km = B_mem @ W_Km^T : [2][32][64] ----------------
__global__ void km_kernel(const float* __restrict__ Bm, const float* __restrict__ WKm) {
    for (int i = threadIdx.x; i < 4096; i += 256) {
        int h = i >> 11, k = (i >> 6) & 31, z = i & 63;
        const float* brow = &Bm[k * 128];
        const float* wrow = &WKm[(h * 64 + z) * 128];
        float acc = 0.f;
#pragma unroll
        for (int dd = 0; dd < 128; dd += 4) {
            float4 b4 = *(const float4*)&brow[dd];
            float4 w4 = *(const float4*)&wrow[dd];
            acc += b4.x * w4.x + b4.y * w4.y + b4.z * w4.z + b4.w * w4.w;
        }
        d_Km[i] = acc;
    }
}

// ---------------- mma.sync GEMM core ----------------
#define TILEB 18432   // 128 * 72 * 2

__device__ __forceinline__ void ld_tile64(const __nv_bfloat16* __restrict__ src, int ld,
                                          char* dst, int tid) {
#pragma unroll
    for (int it = 0; it < 4; it++) {
        int c = it * 256 + tid;            // 1024 chunks of 16B
        int r = c >> 3, c8 = (c & 7) << 3; // row, bf16 col
        *(uint4*)(dst + r * 144 + (c8 << 1)) = *(const uint4*)&src[(size_t)r * ld + c8];
    }
}

__device__ __forceinline__ void gemm_core(
    const __nv_bfloat16* __restrict__ Ah, const __nv_bfloat16* __restrict__ Al, int lda,
    const __nv_bfloat16* __restrict__ Bh, const __nv_bfloat16* __restrict__ Bl, int ldb,
    int Kdim, char* smem, uint32_t sb, int tid, int wid, int lane,
    int wm, int wn, float acc[4][4][4])
{
    uint32_t aoff[4], boff[2];
#pragma unroll
    for (int mt = 0; mt < 4; mt++)
        aoff[mt] = (uint32_t)((wm + mt * 16 + (lane & 15)) * 144 + ((lane >> 4) << 4));
#pragma unroll
    for (int p = 0; p < 2; p++)
        boff[p] = (uint32_t)((wn + p * 16 + ((lane >> 4) << 3) + (lane & 7)) * 144 +
                             (((lane >> 3) & 1) << 4));

    for (int kc = 0; kc < Kdim; kc += 64) {
        ld_tile64(Ah + kc, lda, smem + 0 * TILEB, tid);
        ld_tile64(Al + kc, lda, smem + 1 * TILEB, tid);
        ld_tile64(Bh + kc, ldb, smem + 2 * TILEB, tid);
        ld_tile64(Bl + kc, ldb, smem + 3 * TILEB, tid);
        __syncthreads();
#pragma unroll
        for (int ks = 0; ks < 4; ks++) {
            uint32_t ksb = ks * 32;
            uint32_t ah[4][4], al[4][4], bh[4][2], bl[4][2];
#pragma unroll
            for (int mt = 0; mt < 4; mt++) ldsm4(ah[mt], sb + 0 * TILEB + aoff[mt] + ksb);
#pragma unroll
            for (int p = 0; p < 2; p++) {
                uint32_t r4[4];
                ldsm4(r4, sb + 2 * TILEB + boff[p] + ksb);
                bh[2 * p][0] = r4[0]; bh[2 * p][1] = r4[1];
                bh[2 * p + 1][0] = r4[2]; bh[2 * p + 1][1] = r4[3];
            }
#pragma unroll
            for (int mt = 0; mt < 4; mt++)
#pragma unroll
                for (int nt = 0; nt < 4; nt++) mma16816(acc[mt][nt], ah[mt], bh[nt]);
#pragma unroll
            for (int p = 0; p < 2; p++) {
                uint32_t r4[4];
                ldsm4(r4, sb + 3 * TILEB + boff[p] + ksb);
                bl[2 * p][0] = r4[0]; bl[2 * p][1] = r4[1];
                bl[2 * p + 1][0] = r4[2]; bl[2 * p + 1][1] = r4[3];
            }
#pragma unroll
            for (int mt = 0; mt < 4; mt++)
#pragma unroll
                for (int nt = 0; nt < 4; nt++) mma16816(acc[mt][nt], ah[mt], bl[nt]);
#pragma unroll
            for (int mt = 0; mt < 4; mt++) ldsm4(al[mt], sb + 1 * TILEB + aoff[mt] + ksb);
#pragma unroll
            for (int mt = 0; mt < 4; mt++)
#pragma unroll
                for (int nt = 0; nt < 4; nt++) mma16816(acc[mt][nt], al[mt], bh[nt]);
        }
        __syncthreads();
    }
}

// FWD: Pb[N,896] (bf16) = G @ Wcat^T
__global__ __launch_bounds__(256, 2) void gemm_fwd() {
    extern __shared__ __align__(16) char smem[];
    int tid = threadIdx.x, wid = tid >> 5, lane = tid & 31;
    int row0 = blockIdx.x * 128, col0 = blockIdx.y * 128;
    int wm = (wid & 1) * 64, wn = (wid >> 1) * 32;
    float acc[4][4][4];
#pragma unroll
    for (int i = 0; i < 4; i++)
#pragma unroll
        for (int j = 0; j < 4; j++)
#pragma unroll
            for (int k = 0; k < 4; k++) acc[i][j][k] = 0.f;
    gemm_core(d_Gh + (size_t)row0 * DD, d_Gl + (size_t)row0 * DD, DD,
              d_Wh + (size_t)col0 * DD, d_Wl + (size_t)col0 * DD, DD,
              DD, smem, smem_to_u32(smem), tid, wid, lane, wm, wn, acc);
    int g = lane >> 2, tg = lane & 3;
#pragma unroll
    for (int mt = 0; mt < 4; mt++) {
        int r = row0 + wm + mt * 16 + g;
#pragma unroll
        for (int nt = 0; nt < 4; nt++) {
            int cg = col0 + wn + nt * 8 + tg * 2;
            *(__nv_bfloat162*)&d_Pb[(size_t)r * PW + cg] =
                __floats2bfloat162_rn(acc[mt][nt][0], acc[mt][nt][1]);
            *(__nv_bfloat162*)&d_Pb[(size_t)(r + 8) * PW + cg] =
                __floats2bfloat162_rn(acc[mt][nt][2], acc[mt][nt][3]);
        }
    }
}

// BWD: gG[N,128] (fp32) = gP @ Wcat (presplit gPh/gPl; B = WT)
__global__ __launch_bounds__(256, 2) void gemm_bwd() {
    extern __shared__ __align__(16) char smem[];
    int tid = threadIdx.x, wid = tid >> 5, lane = tid & 31;
    int row0 = blockIdx.x * 128;
    int wm = (wid & 1) * 64, wn = (wid >> 1) * 32;
    float acc[4][4][4];
#pragma unroll
    for (int i = 0; i < 4; i++)
#pragma unroll
        for (int j = 0; j < 4; j++)
#pragma unroll
            for (int k = 0; k < 4; k++) acc[i][j][k] = 0.f;
    gemm_core(d_gPh + (size_t)row0 * PW, d_gPl + (size_t)row0 * PW, PW,
              d_WTh, d_WTl, PW,
              PW, smem, smem_to_u32(smem), tid, wid, lane, wm, wn, acc);
    int g = lane >> 2, tg = lane & 3;
#pragma unroll
    for (int mt = 0; mt < 4; mt++) {
        int r = row0 + wm + mt * 16 + g;
#pragma unroll
        for (int nt = 0; nt < 4; nt++) {
            int cg = wn + nt * 8 + tg * 2;
            *(float2*)&d_gG[(size_t)r * DD + cg] = make_float2(acc[mt][nt][0], acc[mt][nt][1]);
            *(float2*)&d_gG[(size_t)(r + 8) * DD + cg] = make_float2(acc[mt][nt][2], acc[mt][nt][3]);
        }
    }
}

// ---------------- pair forward: w2 = exp(s2), z2 += w2 (warp per edge) ----------------
__global__ __launch_bounds__(256) void s2_fwd(const int* __restrict__ c2, const int* __restrict__ u2,
                                              const float* __restrict__ a2) {
    int e = blockIdx.x * 8 + (threadIdx.x >> 5);
    int lane = threadIdx.x & 31;
    int c = c2[e], u = u2[e];
    float4 q = ld_bf4(&d_Pb[(size_t)c * PW + lane * 4]);
    float4 k = ld_bf4(&d_Pb[(size_t)u * PW + 128 + lane * 4]);
    float p = q.x * k.x + q.y * k.y + q.z * k.z + q.w * k.w;
    p += __shfl_down_sync(0xffffffffu, p, 8);
    p += __shfl_down_sync(0xffffffffu, p, 4);
    p += __shfl_down_sync(0xffffffffu, p, 2);
    p += __shfl_down_sync(0xffffffffu, p, 1);
    if ((lane & 15) == 0) {
        int h = lane >> 4;
        float s = p * 0.125f + a2[e * 2 + h];
        float w = __expf(s);
        d_w2[e * 2 + h] = w;
        atomicAdd(&d_z2[c * 2 + h], w);
    }
}

// ---------------- motif forward (warp per motif) ----------------
__global__ __launch_bounds__(256) void s3_fwd(const int* __restrict__ c3, const int* __restrict__ u3,
                                              const int* __restrict__ v3, const int* __restrict__ tt,
                                              const float* __restrict__ Tt) {
    int m = blockIdx.x * 8 + (threadIdx.x >> 5);
    int lane = threadIdx.x & 31;
    int c = c3[m], u = u3[m], v = v3[m], t = tt[m];
    const __nv_bfloat16* Q  = &d_Pb[(size_t)c * PW + 256];
    const __nv_bfloat16* KU = &d_Pb[(size_t)u * PW + 512];
    const __nv_bfloat16* KV = &d_Pb[(size_t)v * PW + 512];
    const float* T  = &Tt[t * 256];
    float qk[4], tv[4];
#pragma unroll
    for (int hr = 0; hr < 4; hr++) {
        int off = hr * 64 + lane * 2;
        float2 qv  = ld_bf2(&Q[off]);
        float2 kuv = ld_bf2(&KU[off]);
        float2 kvv = ld_bf2(&KV[off]);
        float2 tvv = *(const float2*)&T[off];
        qk[hr] = qv.x * kuv.x + qv.y * kuv.y;
        tv[hr] = tvv.x * kvv.x + tvv.y * kvv.y;
    }
#pragma unroll
    for (int hr = 0; hr < 4; hr++) { qk[hr] = wsum(qk[hr]); tv[hr] = wsum(tv[hr]); }
    if (lane == 0) {
#pragma unroll
        for (int hr = 0; hr < 4; hr++) { d_qk3[m * 4 + hr] = qk[hr]; d_tv3[m * 4 + hr] = tv[hr]; }
#pragma unroll
        for (int h = 0; h < 2; h++) {
            float s = (qk[h * 2] * tv[h * 2] + qk[h * 2 + 1] * tv[h * 2 + 1]) * (1.0f / 64.0f);
            float w = __expf(s);
            d_w3[m * 2 + h] = w;
            atomicAdd(&d_z3[c * 2 + h], w);
        }
    }
}

// ---------------- per-node memory term (fwd+bwd) + 0.5|X|^2 -> d_en ----------------
__global__ __launch_bounds__(128) void node_mem(const float* __restrict__ X) {
    __shared__ float sKm[2 * 32 * 65];
    __shared__ float sQm[4][128];
    __shared__ float sPm[4][2][32];
    int tid = threadIdx.x;
    int w = tid >> 5, lane = tid & 31;
    for (int i = tid; i < 4096; i += 128) {
        int h = i >> 11, k = (i >> 6) & 31, z = i & 63;
        sKm[(h * 32 + k) * 65 + z] = d_Km[i];
    }
    __syncthreads();
    int n = blockIdx.x * 4 + w;
    *(float4*)&sQm[w][lane * 4] = ld_bf4(&d_Pb[(size_t)n * PW + 768 + lane * 4]);
    __syncwarp();
    float smv[2];
#pragma unroll
    for (int h = 0; h < 2; h++) {
        const float* kmrow = &sKm[(h * 32 + lane) * 65];
        const float* qrow = &sQm[w][h * 64];
        float acc = 0.f;
#pragma unroll
        for (int z = 0; z < 64; z++) acc += qrow[z] * kmrow[z];
        smv[h] = acc * 0.125f;
    }
    float e_mem = 0.f;
#pragma unroll
    for (int h = 0; h < 2; h++) {
        float mx = smv[h];
#pragma unroll
        for (int o = 16; o; o >>= 1) mx = fmaxf(mx, __shfl_xor_sync(0xffffffffu, mx, o));
        float ex = __expf(smv[h] - mx);
        float zs = wsum(ex);
        e_mem -= (mx + logf(zs));          // lamm = bm = 1
        sPm[w][h][lane] = ex / zs;
    }
    __syncwarp();
#pragma unroll
    for (int h = 0; h < 2; h++)
#pragma unroll
        for (int t2 = 0; t2 < 2; t2++) {
            int z = lane + 32 * t2;
            float g = 0.f;
#pragma unroll
            for (int k = 0; k < 32; k++) g += sPm[w][h][k] * sKm[(h * 32 + k) * 65 + z];
            d_gP[(size_t)n * PW + 768 + h * 64 + z] = -0.125f * g;
        }
    float4 xv = *(const float4*)&X[n * DD + lane * 4];
    float xs = wsum(xv.x * xv.x + xv.y * xv.y + xv.z * xv.z + xv.w * xv.w);
    if (lane == 0) d_en[n] = 0.5f * xs + e_mem;
}

// ---------------- final per-graph energy (after z2/z3 complete) ----------------
__global__ __launch_bounds__(256) void eg_fin(const int* __restrict__ batch) {
    __shared__ float sE[NG];
    int tid = threadIdx.x;
    if (tid < NG) sE[tid] = 0.f;
    __syncthreads();
    int n = blockIdx.x * 256 + tid;
    float e = d_en[n];
#pragma unroll
    for (int h = 0; h < 2; h++) {
        float z2v = d_z2[n * 2 + h];
        if (z2v > 0.f) e -= logf(z2v);            // lam2 = 1
        float z3v = d_z3[n * 2 + h];
        if (z3v > 0.f) e -= 0.5f * logf(z3v);     // lam3 = 0.5
    }
    atomicAdd(&sE[batch[n]], e);
    __syncthreads();
    if (tid < NG && sE[tid] != 0.f) atomicAdd(&d_Eg[tid], sE[tid]);
}

// ---------------- pair backward (warp per edge) ----------------
__global__ __launch_bounds__(256) void pair_bwd(const int* __restrict__ c2, const int* __restrict__ u2) {
    int e = blockIdx.x * 8 + (threadIdx.x >> 5);
    int lane = threadIdx.x & 31;
    int c = c2[e], u = u2[e];
    int h = lane >> 4;
    float p = d_w2[e * 2 + h] / d_z2[c * 2 + h];
    float cf = -0.125f * p;                       // -lam2 * p / sqrt(HD)
    float4 q = ld_bf4(&d_Pb[(size_t)c * PW + lane * 4]);
    float4 k = ld_bf4(&d_Pb[(size_t)u * PW + 128 + lane * 4]);
    red4(&d_gP[(size_t)c * PW + lane * 4], cf * k.x, cf * k.y, cf * k.z, cf * k.w);
    red4(&d_gP[(size_t)u * PW + 128 + lane * 4], cf * q.x, cf * q.y, cf * q.z, cf * q.w);
}

// ---------------- motif backward (warp per motif) ----------------
__global__ __launch_bounds__(256) void motif_bwd(const int* __restrict__ c3, const int* __restrict__ u3,
                                                 const int* __restrict__ v3, const int* __restrict__ tt,
                                                 const float* __restrict__ Tt) {
    int m = blockIdx.x * 8 + (threadIdx.x >> 5);
    int lane = threadIdx.x & 31;
    int c = c3[m], u = u3[m], v = v3[m], t = tt[m];
    float dqk[4], dtv[4];
#pragma unroll
    for (int h = 0; h < 2; h++) {
        float p = d_w3[m * 2 + h] / d_z3[c * 2 + h];
        float coef = -0.5f * (1.0f / 64.0f) * p;  // -lam3 * p / HD
#pragma unroll
        for (int r = 0; r < 2; r++) {
            int hr = h * 2 + r;
            dqk[hr] = coef * d_tv3[m * 4 + hr];
            dtv[hr] = coef * d_qk3[m * 4 + hr];
        }
    }
#pragma unroll
    for (int hr = 0; hr < 4; hr++) {
        int off = hr * 64 + lane * 2;
        float2 qv  = ld_bf2(&d_Pb[(size_t)c * PW + 256 + off]);
        float2 kuv = ld_bf2(&d_Pb[(size_t)u * PW + 512 + off]);
        float2 kvv = ld_bf2(&d_Pb[(size_t)v * PW + 512 + off]);
        float2 tvv = *(const float2*)&Tt[t * 256 + off];
        red2(&d_gP[(size_t)c * PW + 256 + off], dqk[hr] * kuv.x, dqk[hr] * kuv.y);
        red2(&d_gP[(size_t)u * PW + 512 + off], dqk[hr] * qv.x, dqk[hr] * qv.y);
        red2(&d_gP[(size_t)v * PW + 512 + off], dtv[hr] * tvv.x, dtv[hr] * tvv.y);
    }
}

// ---------------- LN backward + clip + step (warp per node) ----------------
__global__ __launch_bounds__(256) void finalize(const float* __restrict__ X,
                                                const float* __restrict__ gam,
                                                const float* __restrict__ stepp,
                                                float* __restrict__ out) {
    int w = threadIdx.x >> 5, lane = threadIdx.x & 31;
    int n = blockIdx.x * 8 + w;
    float4 x  = *(const float4*)&X[n * DD + lane * 4];
    float4 gg = *(const float4*)&d_gG[n * DD + lane * 4];
    float4 gm = *(const float4*)&gam[lane * 4];
    float mu = d_mu[n], rstd = d_rstd[n];
    float xh0 = (x.x - mu) * rstd, xh1 = (x.y - mu) * rstd, xh2 = (x.z - mu) * rstd, xh3 = (x.w - mu) * rstd;
    float gx0 = gg.x * gm.x, gx1 = gg.y * gm.y, gx2 = gg.z * gm.z, gx3 = gg.w * gm.w;
    float s1 = wsum(gx0 + gx1 + gx2 + gx3) * (1.0f / 128.0f);
    float s2v = wsum(gx0 * xh0 + gx1 * xh1 + gx2 * xh2 + gx3 * xh3) * (1.0f / 128.0f);
    float g0 = x.x + rstd * (gx0 - s1 - xh0 * s2v);
    float g1 = x.y + rstd * (gx1 - s1 - xh1 * s2v);
    float g2 = x.z + rstd * (gx2 - s1 - xh2 * s2v);
    float g3 = x.w + rstd * (gx3 - s1 - xh3 * s2v);
    float gn = sqrtf(wsum(g0 * g0 + g1 * g1 + g2 * g2 + g3 * g3));
    float sc = 1.0f / fmaxf(gn, 1.0f);            // GRAD_CLIP = 1
    float st = stepp[0] * sc;                      // DAMPING = 1
    float xn0 = x.x - st * g0, xn1 = x.y - st * g1, xn2 = x.z - st * g2, xn3 = x.w - st * g3;
    float sn = sqrtf(wsum(xn0 * xn0 + xn1 * xn1 + xn2 * xn2 + xn3 * xn3));
    float sc2 = 10.0f / fmaxf(sn, 10.0f);          // STATE_CLIP = 10
    float4 o = make_float4(xn0 * sc2, xn1 * sc2, xn2 * sc2, xn3 * sc2);
    *(float4*)&out[n * DD + lane * 4] = o;
}

__global__ void eg_copy(float* __restrict__ out) {
    int t = threadIdx.x;
    if (t < NG) out[NN * DD + t] = d_Eg[t];
}

// ---------------- host launch ----------------
extern "C" void kernel_launch(void* const* d_in, const int* in_sizes, int n_in,
                              void* d_out, int out_size) {
    const float* X     = (const float*)d_in[0];
    const int*   c2    = (const int*)d_in[1];
    const int*   u2    = (const int*)d_in[2];
    const int*   c3    = (const int*)d_in[3];
    const int*   u3    = (const int*)d_in[4];
    const int*   v3    = (const int*)d_in[5];
    const int*   tt    = (const int*)d_in[6];
    const int*   batch = (const int*)d_in[7];
    const float* a2    = (const float*)d_in[8];
    const float* step  = (const float*)d_in[9];
    const float* gam   = (const float*)d_in[10];
    const float* bet   = (const float*)d_in[11];
    const float* WQ2   = (const float*)d_in[12];
    const float* WK2   = (const float*)d_in[13];
    const float* WQ3   = (const float*)d_in[14];
    const float* WK3   = (const float*)d_in[15];
    const float* Tt    = (const float*)d_in[16];
    const float* WQm   = (const float*)d_in[17];
    const float* WKm   = (const float*)d_in[18];
    const float* Bm    = (const float*)d_in[19];
    float* out = (float*)d_out;

    static cudaStream_t sE = nullptr, sM = nullptr;
    static cudaEvent_t evFork = nullptr, evE = nullptr, evM = nullptr;
    static int inited = 0;
    if (!inited) {
        cudaFuncSetAttribute(gemm_fwd, cudaFuncAttributeMaxDynamicSharedMemorySize, 4 * TILEB);
        cudaFuncSetAttribute(gemm_bwd, cudaFuncAttributeMaxDynamicSharedMemorySize, 4 * TILEB);
        cudaStreamCreateWithFlags(&sE, cudaStreamNonBlocking);
        cudaStreamCreateWithFlags(&sM, cudaStreamNonBlocking);
        cudaEventCreateWithFlags(&evFork, cudaEventDisableTiming);
        cudaEventCreateWithFlags(&evE, cudaEventDisableTiming);
        cudaEventCreateWithFlags(&evM, cudaEventDisableTiming);
        inited = 1;
    }

    void* p;
    cudaGetSymbolAddress(&p, d_gP); cudaMemsetAsync(p, 0, sizeof(float) * (size_t)NN * PW);
    cudaGetSymbolAddress(&p, d_z2); cudaMemsetAsync(p, 0, sizeof(float) * NN * 2);
    cudaGetSymbolAddress(&p, d_z3); cudaMemsetAsync(p, 0, sizeof(float) * NN * 2);
    cudaGetSymbolAddress(&p, d_Eg); cudaMemsetAsync(p, 0, sizeof(float) * NG);

    ln_fwd<<<NN / 8, 256>>>(X, gam, bet);
    prep_wcat<<<(PW * DD + 255) / 256, 256>>>(WQ2, WK2, WQ3, WK3, WQm);
    km_kernel<<<1, 256>>>(Bm, WKm);
    // Pb = bf16(G @ Wcat^T)
    gemm_fwd<<<dim3(NN / 128, PW / 128), 256, 4 * TILEB>>>();

    // fork: edge chain on sE, motif chain on sM, memory term stays on default
    cudaEventRecord(evFork, 0);
    cudaStreamWaitEvent(sE, evFork, 0);
    cudaStreamWaitEvent(sM, evFork, 0);

    s2_fwd<<<EE / 8, 256, 0, sE>>>(c2, u2, a2);
    pair_bwd<<<EE / 8, 256, 0, sE>>>(c2, u2);
    cudaEventRecord(evE, sE);

    s3_fwd<<<MMOT / 8, 256, 0, sM>>>(c3, u3, v3, tt, Tt);
    motif_bwd<<<MMOT / 8, 256, 0, sM>>>(c3, u3, v3, tt, Tt);
    cudaEventRecord(evM, sM);

    node_mem<<<NN / 4, 128>>>(X);

    // join
    cudaStreamWaitEvent(0, evE, 0);
    cudaStreamWaitEvent(0, evM, 0);

    eg_fin<<<NN / 256, 256>>>(batch);
    gp_conv<<<(NN * PW) / 1024, 256>>>();
    // gG = gP @ Wcat  (presplit bf16; B = WT)
    gemm_bwd<<<dim3(NN / 128, 1), 256, 4 * TILEB>>>();
    finalize<<<NN / 8, 256>>>(X, gam, step, out);
    eg_copy<<<1, 32>>>(out);
}

// round 16
// speedup vs baseline: 1.2700x; 1.1436x over previous
#include <cuda_runtime.h>
#include <cuda_bf16.h>
#include <math.h>
#include <stdint.h>

#define NN    32768
#define DD    128
#define EE    262144
#define MMOT  131072
#define NG    32
#define PW    896      // packed width: Q2[0:128) K2[128:256) Q3[256:512) K3[512:768) Qm[768:896)

// ---------------- scratch (device globals; no allocs allowed) ----------------
__device__ float          d_mu[NN];
__device__ float          d_rstd[NN];
__device__ float          d_en[NN];         // per-node partial energy
__device__ __nv_bfloat16  d_Gb[NN * DD];
__device__ __nv_bfloat16  d_Pb[NN * PW];    // bf16 projections
__device__ float          d_gP[NN * PW];    // fp32 gradient accumulator
__device__ __nv_bfloat16  d_gPb[NN * PW];
__device__ float          d_gG[NN * DD];
__device__ __nv_bfloat16  d_Wb[PW * DD];    // [j][d]
__device__ __nv_bfloat16  d_WTb[DD * PW];   // [d][j]
__device__ float          d_Km[4096];       // [h][k][z] = [2][32][64]
__device__ float          d_w2[EE * 2];     // exp(s2)
__device__ float          d_w3[MMOT * 2];   // exp(s3)
__device__ float          d_qk3[MMOT * 4];
__device__ float          d_tv3[MMOT * 4];
__device__ float          d_z2[NN * 2];
__device__ float          d_z3[NN * 2];
__device__ float          d_Eg[NG];

// ---------------- helpers ----------------
__device__ __forceinline__ uint32_t smem_to_u32(const void* p) {
    uint32_t a;
    asm("{ .reg .u64 t; cvta.to.shared.u64 t, %1; cvt.u32.u64 %0, t; }" : "=r"(a) : "l"(p));
    return a;
}
__device__ __forceinline__ float wsum(float v) {
#pragma unroll
    for (int o = 16; o; o >>= 1) v += __shfl_xor_sync(0xffffffffu, v, o);
    return v;
}
__device__ __forceinline__ void red4(float* a, float x, float y, float z, float w) {
    asm volatile("red.global.add.v4.f32 [%0], {%1,%2,%3,%4};"
                 :: "l"(__cvta_generic_to_global(a)), "f"(x), "f"(y), "f"(z), "f"(w) : "memory");
}
__device__ __forceinline__ void red2(float* a, float x, float y) {
    asm volatile("red.global.add.v2.f32 [%0], {%1,%2};"
                 :: "l"(__cvta_generic_to_global(a)), "f"(x), "f"(y) : "memory");
}
__device__ __forceinline__ uint32_t pack_bf2(__nv_bfloat16 a, __nv_bfloat16 b) {
    __nv_bfloat162 p = __halves2bfloat162(a, b);
    return *(uint32_t*)&p;
}
__device__ __forceinline__ float4 ld_bf4(const __nv_bfloat16* p) {
    uint2 u = *(const uint2*)p;
    float2 fa = __bfloat1622float2(*(__nv_bfloat162*)&u.x);
    float2 fb = __bfloat1622float2(*(__nv_bfloat162*)&u.y);
    return make_float4(fa.x, fa.y, fb.x, fb.y);
}
__device__ __forceinline__ float2 ld_bf2(const __nv_bfloat16* p) {
    __nv_bfloat162 v = *(const __nv_bfloat162*)p;
    return __bfloat1622float2(v);
}
__device__ __forceinline__ void ldsm4(uint32_t* r, uint32_t addr) {
    asm volatile("ldmatrix.sync.aligned.m8n8.x4.shared.b16 {%0,%1,%2,%3}, [%4];"
                 : "=r"(r[0]), "=r"(r[1]), "=r"(r[2]), "=r"(r[3]) : "r"(addr));
}
__device__ __forceinline__ void mma16816(float* c, const uint32_t* a, const uint32_t* b) {
    asm volatile("mma.sync.aligned.m16n8k16.row.col.f32.bf16.bf16.f32 "
                 "{%0,%1,%2,%3}, {%4,%5,%6,%7}, {%8,%9}, {%0,%1,%2,%3};"
                 : "+f"(c[0]), "+f"(c[1]), "+f"(c[2]), "+f"(c[3])
                 : "r"(a[0]), "r"(a[1]), "r"(a[2]), "r"(a[3]), "r"(b[0]), "r"(b[1]));
}

// ---------------- layernorm forward -> G bf16 ----------------
__global__ __launch_bounds__(256) void ln_fwd(const float* __restrict__ X,
                                              const float* __restrict__ gam,
                                              const float* __restrict__ bet) {
    int w = threadIdx.x >> 5, lane = threadIdx.x & 31;
    int n = blockIdx.x * 8 + w;
    float4 x = *(const float4*)&X[n * DD + lane * 4];
    float mu = wsum(x.x + x.y + x.z + x.w) * (1.0f / 128.0f);
    float dx0 = x.x - mu, dx1 = x.y - mu, dx2 = x.z - mu, dx3 = x.w - mu;
    float v = wsum(dx0 * dx0 + dx1 * dx1 + dx2 * dx2 + dx3 * dx3) * (1.0f / 128.0f);
    float rstd = rsqrtf(v + 1e-5f);
    float4 g = *(const float4*)&gam[lane * 4];
    float4 b = *(const float4*)&bet[lane * 4];
    float o0 = g.x * dx0 * rstd + b.x;
    float o1 = g.y * dx1 * rstd + b.y;
    float o2 = g.z * dx2 * rstd + b.z;
    float o3 = g.w * dx3 * rstd + b.w;
    *(uint2*)&d_Gb[n * DD + lane * 4] =
        make_uint2(pack_bf2(__float2bfloat16(o0), __float2bfloat16(o1)),
                   pack_bf2(__float2bfloat16(o2), __float2bfloat16(o3)));
    if (lane == 0) { d_mu[n] = mu; d_rstd[n] = rstd; }
}

// ---------------- pack weights (bf16, direct + transposed) ----------------
__global__ void prep_wcat(const float* __restrict__ WQ2, const float* __restrict__ WK2,
                          const float* __restrict__ WQ3, const float* __restrict__ WK3,
                          const float* __restrict__ WQm) {
    int i = blockIdx.x * 256 + threadIdx.x;
    if (i >= PW * DD) return;
    int j = i >> 7, d = i & 127;
    float v;
    if (j < 128)      v = WQ2[j * 128 + d];
    else if (j < 256) v = WK2[(j - 128) * 128 + d];
    else if (j < 512) v = WQ3[(j - 256) * 128 + d];
    else if (j < 768) v = WK3[(j - 512) * 128 + d];
    else              v = WQm[(j - 768) * 128 + d];
    __nv_bfloat16 h = __float2bfloat16(v);
    d_Wb[i] = h;
    d_WTb[d * PW + j] = h;
}

// ---------------- gP fp32 -> bf16 ----------------
__global__ __launch_bounds__(256) void gp_conv() {
    int i = (blockIdx.x * 256 + threadIdx.x) * 4;
    float4 v = *(const float4*)&d_gP[i];
    *(uint2*)&d_gPb[i] =
        make_uint2(pack_bf2(__float2bfloat16(v.x), __float2bfloat16(v.y)),
                   pack_bf2(__float2bfloat16(v.z), __float2bfloat16(v.w)));
}

// ---------------- Km = B_mem @ W_Km^T : [2][32][64] ----------------
__global__ void km_kernel(const float* __restrict__ Bm, const float* __restrict__ WKm) {
    for (int i = threadIdx.x; i < 4096; i += 256) {
        int h = i >> 11, k = (i >> 6) & 31, z = i & 63;
        const float* brow = &Bm[k * 128];
        const float* wrow = &WKm[(h * 64 + z) * 128];
        float acc = 0.f;
#pragma unroll
        for (int dd = 0; dd < 128; dd += 4) {
            float4 b4 = *(const float4*)&brow[dd];
            float4 w4 = *(const float4*)&wrow[dd];
            acc += b4.x * w4.x + b4.y * w4.y + b4.z * w4.z + b4.w * w4.w;
        }
        d_Km[i] = acc;
    }
}

// ---------------- mma.sync GEMM core (pure bf16, fp32 accum) ----------------
// C[128,128] tile = A[128,K] @ B[128,K]^T; smem tiles [128][72] bf16 (row stride 144B).
#define TILEB 18432   // 128 * 72 * 2

__device__ __forceinline__ void ld_tile64(const __nv_bfloat16* __restrict__ src, int ld,
                                          char* dst, int tid) {
#pragma unroll
    for (int it = 0; it < 4; it++) {
        int c = it * 256 + tid;            // 1024 chunks of 16B
        int r = c >> 3, c8 = (c & 7) << 3; // row, bf16 col
        *(uint4*)(dst + r * 144 + (c8 << 1)) = *(const uint4*)&src[(size_t)r * ld + c8];
    }
}

__device__ __forceinline__ void gemm_core(
    const __nv_bfloat16* __restrict__ A, int lda,
    const __nv_bfloat16* __restrict__ B, int ldb,
    int Kdim, char* smem, uint32_t sb, int tid, int lane,
    int wm, int wn, float acc[4][4][4])
{
    uint32_t aoff[4], boff[2];
#pragma unroll
    for (int mt = 0; mt < 4; mt++)
        aoff[mt] = (uint32_t)((wm + mt * 16 + (lane & 15)) * 144 + ((lane >> 4) << 4));
#pragma unroll
    for (int p = 0; p < 2; p++)
        boff[p] = (uint32_t)((wn + p * 16 + ((lane >> 4) << 3) + (lane & 7)) * 144 +
                             (((lane >> 3) & 1) << 4));

    for (int kc = 0; kc < Kdim; kc += 64) {
        ld_tile64(A + kc, lda, smem + 0 * TILEB, tid);
        ld_tile64(B + kc, ldb, smem + 1 * TILEB, tid);
        __syncthreads();
#pragma unroll
        for (int ks = 0; ks < 4; ks++) {
            uint32_t ksb = ks * 32;
            uint32_t ah[4][4], bh[4][2];
#pragma unroll
            for (int mt = 0; mt < 4; mt++) ldsm4(ah[mt], sb + 0 * TILEB + aoff[mt] + ksb);
#pragma unroll
            for (int p = 0; p < 2; p++) {
                uint32_t r4[4];
                ldsm4(r4, sb + 1 * TILEB + boff[p] + ksb);
                bh[2 * p][0] = r4[0]; bh[2 * p][1] = r4[1];
                bh[2 * p + 1][0] = r4[2]; bh[2 * p + 1][1] = r4[3];
            }
#pragma unroll
            for (int mt = 0; mt < 4; mt++)
#pragma unroll
                for (int nt = 0; nt < 4; nt++) mma16816(acc[mt][nt], ah[mt], bh[nt]);
        }
        __syncthreads();
    }
}

// FWD: Pb[N,896] (bf16) = G @ Wcat^T
__global__ __launch_bounds__(256, 2) void gemm_fwd() {
    extern __shared__ __align__(16) char smem[];
    int tid = threadIdx.x, wid = tid >> 5, lane = tid & 31;
    int row0 = blockIdx.x * 128, col0 = blockIdx.y * 128;
    int wm = (wid & 1) * 64, wn = (wid >> 1) * 32;
    float acc[4][4][4];
#pragma unroll
    for (int i = 0; i < 4; i++)
#pragma unroll
        for (int j = 0; j < 4; j++)
#pragma unroll
            for (int k = 0; k < 4; k++) acc[i][j][k] = 0.f;
    gemm_core(d_Gb + (size_t)row0 * DD, DD,
              d_Wb + (size_t)col0 * DD, DD,
              DD, smem, smem_to_u32(smem), tid, lane, wm, wn, acc);
    int g = lane >> 2, tg = lane & 3;
#pragma unroll
    for (int mt = 0; mt < 4; mt++) {
        int r = row0 + wm + mt * 16 + g;
#pragma unroll
        for (int nt = 0; nt < 4; nt++) {
            int cg = col0 + wn + nt * 8 + tg * 2;
            *(__nv_bfloat162*)&d_Pb[(size_t)r * PW + cg] =
                __floats2bfloat162_rn(acc[mt][nt][0], acc[mt][nt][1]);
            *(__nv_bfloat162*)&d_Pb[(size_t)(r + 8) * PW + cg] =
                __floats2bfloat162_rn(acc[mt][nt][2], acc[mt][nt][3]);
        }
    }
}

// BWD: gG[N,128] (fp32) = gP @ Wcat (bf16 gPb; B = WT)
__global__ __launch_bounds__(256, 2) void gemm_bwd() {
    extern __shared__ __align__(16) char smem[];
    int tid = threadIdx.x, wid = tid >> 5, lane = tid & 31;
    int row0 = blockIdx.x * 128;
    int wm = (wid & 1) * 64, wn = (wid >> 1) * 32;
    float acc[4][4][4];
#pragma unroll
    for (int i = 0; i < 4; i++)
#pragma unroll
        for (int j = 0; j < 4; j++)
#pragma unroll
            for (int k = 0; k < 4; k++) acc[i][j][k] = 0.f;
    gemm_core(d_gPb + (size_t)row0 * PW, PW,
              d_WTb, PW,
              PW, smem, smem_to_u32(smem), tid, lane, wm, wn, acc);
    int g = lane >> 2, tg = lane & 3;
#pragma unroll
    for (int mt = 0; mt < 4; mt++) {
        int r = row0 + wm + mt * 16 + g;
#pragma unroll
        for (int nt = 0; nt < 4; nt++) {
            int cg = wn + nt * 8 + tg * 2;
            *(float2*)&d_gG[(size_t)r * DD + cg] = make_float2(acc[mt][nt][0], acc[mt][nt][1]);
            *(float2*)&d_gG[(size_t)(r + 8) * DD + cg] = make_float2(acc[mt][nt][2], acc[mt][nt][3]);
        }
    }
}

// ---------------- pair forward: w2 = exp(s2), z2 += w2 (warp per edge) ----------------
__global__ __launch_bounds__(256) void s2_fwd(const int* __restrict__ c2, const int* __restrict__ u2,
                                              const float* __restrict__ a2) {
    int e = blockIdx.x * 8 + (threadIdx.x >> 5);
    int lane = threadIdx.x & 31;
    int c = c2[e], u = u2[e];
    float4 q = ld_bf4(&d_Pb[(size_t)c * PW + lane * 4]);
    float4 k = ld_bf4(&d_Pb[(size_t)u * PW + 128 + lane * 4]);
    float p = q.x * k.x + q.y * k.y + q.z * k.z + q.w * k.w;
    p += __shfl_down_sync(0xffffffffu, p, 8);
    p += __shfl_down_sync(0xffffffffu, p, 4);
    p += __shfl_down_sync(0xffffffffu, p, 2);
    p += __shfl_down_sync(0xffffffffu, p, 1);
    if ((lane & 15) == 0) {
        int h = lane >> 4;
        float s = p * 0.125f + a2[e * 2 + h];
        float w = __expf(s);
        d_w2[e * 2 + h] = w;
        atomicAdd(&d_z2[c * 2 + h], w);
    }
}

// ---------------- motif forward (warp per motif) ----------------
__global__ __launch_bounds__(256) void s3_fwd(const int* __restrict__ c3, const int* __restrict__ u3,
                                              const int* __restrict__ v3, const int* __restrict__ tt,
                                              const float* __restrict__ Tt) {
    int m = blockIdx.x * 8 + (threadIdx.x >> 5);
    int lane = threadIdx.x & 31;
    int c = c3[m], u = u3[m], v = v3[m], t = tt[m];
    const __nv_bfloat16* Q  = &d_Pb[(size_t)c * PW + 256];
    const __nv_bfloat16* KU = &d_Pb[(size_t)u * PW + 512];
    const __nv_bfloat16* KV = &d_Pb[(size_t)v * PW + 512];
    const float* T  = &Tt[t * 256];
    float qk[4], tv[4];
#pragma unroll
    for (int hr = 0; hr < 4; hr++) {
        int off = hr * 64 + lane * 2;
        float2 qv  = ld_bf2(&Q[off]);
        float2 kuv = ld_bf2(&KU[off]);
        float2 kvv = ld_bf2(&KV[off]);
        float2 tvv = *(const float2*)&T[off];
        qk[hr] = qv.x * kuv.x + qv.y * kuv.y;
        tv[hr] = tvv.x * kvv.x + tvv.y * kvv.y;
    }
#pragma unroll
    for (int hr = 0; hr < 4; hr++) { qk[hr] = wsum(qk[hr]); tv[hr] = wsum(tv[hr]); }
    if (lane == 0) {
#pragma unroll
        for (int hr = 0; hr < 4; hr++) { d_qk3[m * 4 + hr] = qk[hr]; d_tv3[m * 4 + hr] = tv[hr]; }
#pragma unroll
        for (int h = 0; h < 2; h++) {
            float s = (qk[h * 2] * tv[h * 2] + qk[h * 2 + 1] * tv[h * 2 + 1]) * (1.0f / 64.0f);
            float w = __expf(s);
            d_w3[m * 2 + h] = w;
            atomicAdd(&d_z3[c * 2 + h], w);
        }
    }
}

// ---------------- per-node memory term (fwd+bwd) + 0.5|X|^2 -> d_en ----------------
__global__ __launch_bounds__(128) void node_mem(const float* __restrict__ X) {
    __shared__ float sKm[2 * 32 * 65];
    __shared__ float sQm[4][128];
    __shared__ float sPm[4][2][32];
    int tid = threadIdx.x;
    int w = tid >> 5, lane = tid & 31;
    for (int i = tid; i < 4096; i += 128) {
        int h = i >> 11, k = (i >> 6) & 31, z = i & 63;
        sKm[(h * 32 + k) * 65 + z] = d_Km[i];
    }
    __syncthreads();
    int n = blockIdx.x * 4 + w;
    *(float4*)&sQm[w][lane * 4] = ld_bf4(&d_Pb[(size_t)n * PW + 768 + lane * 4]);
    __syncwarp();
    float smv[2];
#pragma unroll
    for (int h = 0; h < 2; h++) {
        const float* kmrow = &sKm[(h * 32 + lane) * 65];
        const float* qrow = &sQm[w][h * 64];
        float acc = 0.f;
#pragma unroll
        for (int z = 0; z < 64; z++) acc += qrow[z] * kmrow[z];
        smv[h] = acc * 0.125f;
    }
    float e_mem = 0.f;
#pragma unroll
    for (int h = 0; h < 2; h++) {
        float mx = smv[h];
#pragma unroll
        for (int o = 16; o; o >>= 1) mx = fmaxf(mx, __shfl_xor_sync(0xffffffffu, mx, o));
        float ex = __expf(smv[h] - mx);
        float zs = wsum(ex);
        e_mem -= (mx + logf(zs));          // lamm = bm = 1
        sPm[w][h][lane] = ex / zs;
    }
    __syncwarp();
#pragma unroll
    for (int h = 0; h < 2; h++)
#pragma unroll
        for (int t2 = 0; t2 < 2; t2++) {
            int z = lane + 32 * t2;
            float g = 0.f;
#pragma unroll
            for (int k = 0; k < 32; k++) g += sPm[w][h][k] * sKm[(h * 32 + k) * 65 + z];
            d_gP[(size_t)n * PW + 768 + h * 64 + z] = -0.125f * g;
        }
    float4 xv = *(const float4*)&X[n * DD + lane * 4];
    float xs = wsum(xv.x * xv.x + xv.y * xv.y + xv.z * xv.z + xv.w * xv.w);
    if (lane == 0) d_en[n] = 0.5f * xs + e_mem;
}

// ---------------- final per-graph energy (after z2/z3 complete) ----------------
__global__ __launch_bounds__(256) void eg_fin(const int* __restrict__ batch) {
    __shared__ float sE[NG];
    int tid = threadIdx.x;
    if (tid < NG) sE[tid] = 0.f;
    __syncthreads();
    int n = blockIdx.x * 256 + tid;
    float e = d_en[n];
#pragma unroll
    for (int h = 0; h < 2; h++) {
        float z2v = d_z2[n * 2 + h];
        if (z2v > 0.f) e -= logf(z2v);            // lam2 = 1
        float z3v = d_z3[n * 2 + h];
        if (z3v > 0.f) e -= 0.5f * logf(z3v);     // lam3 = 0.5
    }
    atomicAdd(&sE[batch[n]], e);
    __syncthreads();
    if (tid < NG && sE[tid] != 0.f) atomicAdd(&d_Eg[tid], sE[tid]);
}

// ---------------- pair backward (warp per edge) ----------------
__global__ __launch_bounds__(256) void pair_bwd(const int* __restrict__ c2, const int* __restrict__ u2) {
    int e = blockIdx.x * 8 + (threadIdx.x >> 5);
    int lane = threadIdx.x & 31;
    int c = c2[e], u = u2[e];
    int h = lane >> 4;
    float p = d_w2[e * 2 + h] / d_z2[c * 2 + h];
    float cf = -0.125f * p;                       // -lam2 * p / sqrt(HD)
    float4 q = ld_bf4(&d_Pb[(size_t)c * PW + lane * 4]);
    float4 k = ld_bf4(&d_Pb[(size_t)u * PW + 128 + lane * 4]);
    red4(&d_gP[(size_t)c * PW + lane * 4], cf * k.x, cf * k.y, cf * k.z, cf * k.w);
    red4(&d_gP[(size_t)u * PW + 128 + lane * 4], cf * q.x, cf * q.y, cf * q.z, cf * q.w);
}

// ---------------- motif backward (warp per motif) ----------------
__global__ __launch_bounds__(256) void motif_bwd(const int* __restrict__ c3, const int* __restrict__ u3,
                                                 const int* __restrict__ v3, const int* __restrict__ tt,
                                                 const float* __restrict__ Tt) {
    int m = blockIdx.x * 8 + (threadIdx.x >> 5);
    int lane = threadIdx.x & 31;
    int c = c3[m], u = u3[m], v = v3[m], t = tt[m];
    float dqk[4], dtv[4];
#pragma unroll
    for (int h = 0; h < 2; h++) {
        float p = d_w3[m * 2 + h] / d_z3[c * 2 + h];
        float coef = -0.5f * (1.0f / 64.0f) * p;  // -lam3 * p / HD
#pragma unroll
        for (int r = 0; r < 2; r++) {
            int hr = h * 2 + r;
            dqk[hr] = coef * d_tv3[m * 4 + hr];
            dtv[hr] = coef * d_qk3[m * 4 + hr];
        }
    }
#pragma unroll
    for (int hr = 0; hr < 4; hr++) {
        int off = hr * 64 + lane * 2;
        float2 qv  = ld_bf2(&d_Pb[(size_t)c * PW + 256 + off]);
        float2 kuv = ld_bf2(&d_Pb[(size_t)u * PW + 512 + off]);
        float2 kvv = ld_bf2(&d_Pb[(size_t)v * PW + 512 + off]);
        float2 tvv = *(const float2*)&Tt[t * 256 + off];
        red2(&d_gP[(size_t)c * PW + 256 + off], dqk[hr] * kuv.x, dqk[hr] * kuv.y);
        red2(&d_gP[(size_t)u * PW + 512 + off], dqk[hr] * qv.x, dqk[hr] * qv.y);
        red2(&d_gP[(size_t)v * PW + 512 + off], dtv[hr] * tvv.x, dtv[hr] * tvv.y);
    }
}

// ---------------- LN backward + clip + step (warp per node) ----------------
__global__ __launch_bounds__(256) void finalize(const float* __restrict__ X,
                                                const float* __restrict__ gam,
                                                const float* __restrict__ stepp,
                                                float* __restrict__ out) {
    int w = threadIdx.x >> 5, lane = threadIdx.x & 31;
    int n = blockIdx.x * 8 + w;
    float4 x  = *(const float4*)&X[n * DD + lane * 4];
    float4 gg = *(const float4*)&d_gG[n * DD + lane * 4];
    float4 gm = *(const float4*)&gam[lane * 4];
    float mu = d_mu[n], rstd = d_rstd[n];
    float xh0 = (x.x - mu) * rstd, xh1 = (x.y - mu) * rstd, xh2 = (x.z - mu) * rstd, xh3 = (x.w - mu) * rstd;
    float gx0 = gg.x * gm.x, gx1 = gg.y * gm.y, gx2 = gg.z * gm.z, gx3 = gg.w * gm.w;
    float s1 = wsum(gx0 + gx1 + gx2 + gx3) * (1.0f / 128.0f);
    float s2v = wsum(gx0 * xh0 + gx1 * xh1 + gx2 * xh2 + gx3 * xh3) * (1.0f / 128.0f);
    float g0 = x.x + rstd * (gx0 - s1 - xh0 * s2v);
    float g1 = x.y + rstd * (gx1 - s1 - xh1 * s2v);
    float g2 = x.z + rstd * (gx2 - s1 - xh2 * s2v);
    float g3 = x.w + rstd * (gx3 - s1 - xh3 * s2v);
    float gn = sqrtf(wsum(g0 * g0 + g1 * g1 + g2 * g2 + g3 * g3));
    float sc = 1.0f / fmaxf(gn, 1.0f);            // GRAD_CLIP = 1
    float st = stepp[0] * sc;                      // DAMPING = 1
    float xn0 = x.x - st * g0, xn1 = x.y - st * g1, xn2 = x.z - st * g2, xn3 = x.w - st * g3;
    float sn = sqrtf(wsum(xn0 * xn0 + xn1 * xn1 + xn2 * xn2 + xn3 * xn3));
    float sc2 = 10.0f / fmaxf(sn, 10.0f);          // STATE_CLIP = 10
    float4 o = make_float4(xn0 * sc2, xn1 * sc2, xn2 * sc2, xn3 * sc2);
    *(float4*)&out[n * DD + lane * 4] = o;
}

__global__ void eg_copy(float* __restrict__ out) {
    int t = threadIdx.x;
    if (t < NG) out[NN * DD + t] = d_Eg[t];
}

// ---------------- host launch ----------------
extern "C" void kernel_launch(void* const* d_in, const int* in_sizes, int n_in,
                              void* d_out, int out_size) {
    const float* X     = (const float*)d_in[0];
    const int*   c2    = (const int*)d_in[1];
    const int*   u2    = (const int*)d_in[2];
    const int*   c3    = (const int*)d_in[3];
    const int*   u3    = (const int*)d_in[4];
    const int*   v3    = (const int*)d_in[5];
    const int*   tt    = (const int*)d_in[6];
    const int*   batch = (const int*)d_in[7];
    const float* a2    = (const float*)d_in[8];
    const float* step  = (const float*)d_in[9];
    const float* gam   = (const float*)d_in[10];
    const float* bet   = (const float*)d_in[11];
    const float* WQ2   = (const float*)d_in[12];
    const float* WK2   = (const float*)d_in[13];
    const float* WQ3   = (const float*)d_in[14];
    const float* WK3   = (const float*)d_in[15];
    const float* Tt    = (const float*)d_in[16];
    const float* WQm   = (const float*)d_in[17];
    const float* WKm   = (const float*)d_in[18];
    const float* Bm    = (const float*)d_in[19];
    float* out = (float*)d_out;

    static cudaStream_t sE = nullptr, sM = nullptr;
    static cudaEvent_t evFork = nullptr, evE = nullptr, evM = nullptr;
    static int inited = 0;
    if (!inited) {
        cudaFuncSetAttribute(gemm_fwd, cudaFuncAttributeMaxDynamicSharedMemorySize, 2 * TILEB);
        cudaFuncSetAttribute(gemm_bwd, cudaFuncAttributeMaxDynamicSharedMemorySize, 2 * TILEB);
        cudaStreamCreateWithFlags(&sE, cudaStreamNonBlocking);
        cudaStreamCreateWithFlags(&sM, cudaStreamNonBlocking);
        cudaEventCreateWithFlags(&evFork, cudaEventDisableTiming);
        cudaEventCreateWithFlags(&evE, cudaEventDisableTiming);
        cudaEventCreateWithFlags(&evM, cudaEventDisableTiming);
        inited = 1;
    }

    void* p;
    cudaGetSymbolAddress(&p, d_gP); cudaMemsetAsync(p, 0, sizeof(float) * (size_t)NN * PW);
    cudaGetSymbolAddress(&p, d_z2); cudaMemsetAsync(p, 0, sizeof(float) * NN * 2);
    cudaGetSymbolAddress(&p, d_z3); cudaMemsetAsync(p, 0, sizeof(float) * NN * 2);
    cudaGetSymbolAddress(&p, d_Eg); cudaMemsetAsync(p, 0, sizeof(float) * NG);

    ln_fwd<<<NN / 8, 256>>>(X, gam, bet);
    prep_wcat<<<(PW * DD + 255) / 256, 256>>>(WQ2, WK2, WQ3, WK3, WQm);
    km_kernel<<<1, 256>>>(Bm, WKm);
    // Pb = bf16(G @ Wcat^T)
    gemm_fwd<<<dim3(NN / 128, PW / 128), 256, 2 * TILEB>>>();

    // fork: edge chain on sE, motif chain on sM, memory term stays on default
    cudaEventRecord(evFork, 0);
    cudaStreamWaitEvent(sE, evFork, 0);
    cudaStreamWaitEvent(sM, evFork, 0);

    s2_fwd<<<EE / 8, 256, 0, sE>>>(c2, u2, a2);
    pair_bwd<<<EE / 8, 256, 0, sE>>>(c2, u2);
    cudaEventRecord(evE, sE);

    s3_fwd<<<MMOT / 8, 256, 0, sM>>>(c3, u3, v3, tt, Tt);
    motif_bwd<<<MMOT / 8, 256, 0, sM>>>(c3, u3, v3, tt, Tt);
    cudaEventRecord(evM, sM);

    node_mem<<<NN / 4, 128>>>(X);

    // join
    cudaStreamWaitEvent(0, evE, 0);
    cudaStreamWaitEvent(0, evM, 0);

    eg_fin<<<NN / 256, 256>>>(batch);
    gp_conv<<<(NN * PW) / 1024, 256>>>();
    // gG = gP @ Wcat  (bf16 gPb; B = WT)
    gemm_bwd<<<dim3(NN / 128, 1), 256, 2 * TILEB>>>();
    finalize<<<NN / 8, 256>>>(X, gam, step, out);
    eg_copy<<<1, 32>>>(out);
}

// round 17
// speedup vs baseline: 1.3087x; 1.0305x over previous
#include <cuda_runtime.h>
#include <cuda_bf16.h>
#include <math.h>
#include <stdint.h>

#define NN    32768
#define DD    128
#define EE    262144
#define MMOT  131072
#define NG    32
#define PW    896      // packed width: Q2[0:128) K2[128:256) Q3[256:512) K3[512:768) Qm[768:896)

// ---------------- scratch (device globals; no allocs allowed) ----------------
__device__ float          d_mu[NN];
__device__ float          d_rstd[NN];
__device__ float          d_en[NN];         // per-node partial energy
__device__ __nv_bfloat16  d_Gb[NN * DD];
__device__ __nv_bfloat16  d_Pb[NN * PW];    // bf16 projections
__device__ float          d_gP[NN * PW];    // fp32 gradient accumulator
__device__ __nv_bfloat16  d_gPb[NN * PW];
__device__ float          d_gG[NN * DD];
__device__ __nv_bfloat16  d_Wb[PW * DD];    // [j][d]
__device__ __nv_bfloat16  d_WTb[DD * PW];   // [d][j]
__device__ float          d_Km[4096];       // [h][k][z] = [2][32][64]
__device__ float          d_w2[EE * 2];     // exp(s2)
__device__ float          d_w3[MMOT * 2];   // exp(s3)
__device__ float          d_qk3[MMOT * 4];
__device__ float          d_tv3[MMOT * 4];
__device__ float          d_z2[NN * 2];
__device__ float          d_z3[NN * 2];
__device__ float          d_Eg[NG];

// ---------------- helpers ----------------
__device__ __forceinline__ uint32_t smem_to_u32(const void* p) {
    uint32_t a;
    asm("{ .reg .u64 t; cvta.to.shared.u64 t, %1; cvt.u32.u64 %0, t; }" : "=r"(a) : "l"(p));
    return a;
}
__device__ __forceinline__ float wsum(float v) {
#pragma unroll
    for (int o = 16; o; o >>= 1) v += __shfl_xor_sync(0xffffffffu, v, o);
    return v;
}
__device__ __forceinline__ void red4(float* a, float x, float y, float z, float w) {
    asm volatile("red.global.add.v4.f32 [%0], {%1,%2,%3,%4};"
                 :: "l"(__cvta_generic_to_global(a)), "f"(x), "f"(y), "f"(z), "f"(w) : "memory");
}
__device__ __forceinline__ void red2(float* a, float x, float y) {
    asm volatile("red.global.add.v2.f32 [%0], {%1,%2};"
                 :: "l"(__cvta_generic_to_global(a)), "f"(x), "f"(y) : "memory");
}
__device__ __forceinline__ uint32_t pack_bf2(__nv_bfloat16 a, __nv_bfloat16 b) {
    __nv_bfloat162 p = __halves2bfloat162(a, b);
    return *(uint32_t*)&p;
}
__device__ __forceinline__ float4 ld_bf4(const __nv_bfloat16* p) {
    uint2 u = *(const uint2*)p;
    float2 fa = __bfloat1622float2(*(__nv_bfloat162*)&u.x);
    float2 fb = __bfloat1622float2(*(__nv_bfloat162*)&u.y);
    return make_float4(fa.x, fa.y, fb.x, fb.y);
}
__device__ __forceinline__ float2 ld_bf2(const __nv_bfloat16* p) {
    __nv_bfloat162 v = *(const __nv_bfloat162*)p;
    return __bfloat1622float2(v);
}
__device__ __forceinline__ void ldsm4(uint32_t* r, uint32_t addr) {
    asm volatile("ldmatrix.sync.aligned.m8n8.x4.shared.b16 {%0,%1,%2,%3}, [%4];"
                 : "=r"(r[0]), "=r"(r[1]), "=r"(r[2]), "=r"(r[3]) : "r"(addr));
}
__device__ __forceinline__ void mma16816(float* c, const uint32_t* a, const uint32_t* b) {
    asm volatile("mma.sync.aligned.m16n8k16.row.col.f32.bf16.bf16.f32 "
                 "{%0,%1,%2,%3}, {%4,%5,%6,%7}, {%8,%9}, {%0,%1,%2,%3};"
                 : "+f"(c[0]), "+f"(c[1]), "+f"(c[2]), "+f"(c[3])
                 : "r"(a[0]), "r"(a[1]), "r"(a[2]), "r"(a[3]), "r"(b[0]), "r"(b[1]));
}

// ---------------- layernorm forward -> G bf16 ----------------
__global__ __launch_bounds__(256) void ln_fwd(const float* __restrict__ X,
                                              const float* __restrict__ gam,
                                              const float* __restrict__ bet) {
    int w = threadIdx.x >> 5, lane = threadIdx.x & 31;
    int n = blockIdx.x * 8 + w;
    float4 x = *(const float4*)&X[n * DD + lane * 4];
    float mu = wsum(x.x + x.y + x.z + x.w) * (1.0f / 128.0f);
    float dx0 = x.x - mu, dx1 = x.y - mu, dx2 = x.z - mu, dx3 = x.w - mu;
    float v = wsum(dx0 * dx0 + dx1 * dx1 + dx2 * dx2 + dx3 * dx3) * (1.0f / 128.0f);
    float rstd = rsqrtf(v + 1e-5f);
    float4 g = *(const float4*)&gam[lane * 4];
    float4 b = *(const float4*)&bet[lane * 4];
    float o0 = g.x * dx0 * rstd + b.x;
    float o1 = g.y * dx1 * rstd + b.y;
    float o2 = g.z * dx2 * rstd + b.z;
    float o3 = g.w * dx3 * rstd + b.w;
    *(uint2*)&d_Gb[n * DD + lane * 4] =
        make_uint2(pack_bf2(__float2bfloat16(o0), __float2bfloat16(o1)),
                   pack_bf2(__float2bfloat16(o2), __float2bfloat16(o3)));
    if (lane == 0) { d_mu[n] = mu; d_rstd[n] = rstd; }
}

// ---------------- pack weights (bf16, direct + transposed) ----------------
__global__ void prep_wcat(const float* __restrict__ WQ2, const float* __restrict__ WK2,
                          const float* __restrict__ WQ3, const float* __restrict__ WK3,
                          const float* __restrict__ WQm) {
    int i = blockIdx.x * 256 + threadIdx.x;
    if (i >= PW * DD) return;
    int j = i >> 7, d = i & 127;
    float v;
    if (j < 128)      v = WQ2[j * 128 + d];
    else if (j < 256) v = WK2[(j - 128) * 128 + d];
    else if (j < 512) v = WQ3[(j - 256) * 128 + d];
    else if (j < 768) v = WK3[(j - 512) * 128 + d];
    else              v = WQm[(j - 768) * 128 + d];
    __nv_bfloat16 h = __float2bfloat16(v);
    d_Wb[i] = h;
    d_WTb[d * PW + j] = h;
}

// ---------------- gP fp32 -> bf16 ----------------
__global__ __launch_bounds__(256) void gp_conv() {
    int i = (blockIdx.x * 256 + threadIdx.x) * 4;
    float4 v = *(const float4*)&d_gP[i];
    *(uint2*)&d_gPb[i] =
        make_uint2(pack_bf2(__float2bfloat16(v.x), __float2bfloat16(v.y)),
                   pack_bf2(__float2bfloat16(v.z), __float2bfloat16(v.w)));
}

// ---------------- Km = B_mem @ W_Km^T : [2][32][64] ----------------
__global__ void km_kernel(const float* __restrict__ Bm, const float* __restrict__ WKm) {
    for (int i = threadIdx.x; i < 4096; i += 256) {
        int h = i >> 11, k = (i >> 6) & 31, z = i & 63;
        const float* brow = &Bm[k * 128];
        const float* wrow = &WKm[(h * 64 + z) * 128];
        float acc = 0.f;
#pragma unroll
        for (int dd = 0; dd < 128; dd += 4) {
            float4 b4 = *(const float4*)&brow[dd];
            float4 w4 = *(const float4*)&wrow[dd];
            acc += b4.x * w4.x + b4.y * w4.y + b4.z * w4.z + b4.w * w4.w;
        }
        d_Km[i] = acc;
    }
}

// ---------------- mma.sync GEMM core (pure bf16, fp32 accum) ----------------
#define TILEB 18432   // 128 * 72 * 2

__device__ __forceinline__ void ld_tile64(const __nv_bfloat16* __restrict__ src, int ld,
                                          char* dst, int tid) {
#pragma unroll
    for (int it = 0; it < 4; it++) {
        int c = it * 256 + tid;            // 1024 chunks of 16B
        int r = c >> 3, c8 = (c & 7) << 3; // row, bf16 col
        *(uint4*)(dst + r * 144 + (c8 << 1)) = *(const uint4*)&src[(size_t)r * ld + c8];
    }
}

__device__ __forceinline__ void gemm_core(
    const __nv_bfloat16* __restrict__ A, int lda,
    const __nv_bfloat16* __restrict__ B, int ldb,
    int Kdim, char* smem, uint32_t sb, int tid, int lane,
    int wm, int wn, float acc[4][4][4])
{
    uint32_t aoff[4], boff[2];
#pragma unroll
    for (int mt = 0; mt < 4; mt++)
        aoff[mt] = (uint32_t)((wm + mt * 16 + (lane & 15)) * 144 + ((lane >> 4) << 4));
#pragma unroll
    for (int p = 0; p < 2; p++)
        boff[p] = (uint32_t)((wn + p * 16 + ((lane >> 4) << 3) + (lane & 7)) * 144 +
                             (((lane >> 3) & 1) << 4));

    for (int kc = 0; kc < Kdim; kc += 64) {
        ld_tile64(A + kc, lda, smem + 0 * TILEB, tid);
        ld_tile64(B + kc, ldb, smem + 1 * TILEB, tid);
        __syncthreads();
#pragma unroll
        for (int ks = 0; ks < 4; ks++) {
            uint32_t ksb = ks * 32;
            uint32_t ah[4][4], bh[4][2];
#pragma unroll
            for (int mt = 0; mt < 4; mt++) ldsm4(ah[mt], sb + 0 * TILEB + aoff[mt] + ksb);
#pragma unroll
            for (int p = 0; p < 2; p++) {
                uint32_t r4[4];
                ldsm4(r4, sb + 1 * TILEB + boff[p] + ksb);
                bh[2 * p][0] = r4[0]; bh[2 * p][1] = r4[1];
                bh[2 * p + 1][0] = r4[2]; bh[2 * p + 1][1] = r4[3];
            }
#pragma unroll
            for (int mt = 0; mt < 4; mt++)
#pragma unroll
                for (int nt = 0; nt < 4; nt++) mma16816(acc[mt][nt], ah[mt], bh[nt]);
        }
        __syncthreads();
    }
}

// FWD: Pb[N,896] (bf16) = G @ Wcat^T
__global__ __launch_bounds__(256, 2) void gemm_fwd() {
    extern __shared__ __align__(16) char smem[];
    int tid = threadIdx.x, wid = tid >> 5, lane = tid & 31;
    int row0 = blockIdx.x * 128, col0 = blockIdx.y * 128;
    int wm = (wid & 1) * 64, wn = (wid >> 1) * 32;
    float acc[4][4][4];
#pragma unroll
    for (int i = 0; i < 4; i++)
#pragma unroll
        for (int j = 0; j < 4; j++)
#pragma unroll
            for (int k = 0; k < 4; k++) acc[i][j][k] = 0.f;
    gemm_core(d_Gb + (size_t)row0 * DD, DD,
              d_Wb + (size_t)col0 * DD, DD,
              DD, smem, smem_to_u32(smem), tid, lane, wm, wn, acc);
    int g = lane >> 2, tg = lane & 3;
#pragma unroll
    for (int mt = 0; mt < 4; mt++) {
        int r = row0 + wm + mt * 16 + g;
#pragma unroll
        for (int nt = 0; nt < 4; nt++) {
            int cg = col0 + wn + nt * 8 + tg * 2;
            *(__nv_bfloat162*)&d_Pb[(size_t)r * PW + cg] =
                __floats2bfloat162_rn(acc[mt][nt][0], acc[mt][nt][1]);
            *(__nv_bfloat162*)&d_Pb[(size_t)(r + 8) * PW + cg] =
                __floats2bfloat162_rn(acc[mt][nt][2], acc[mt][nt][3]);
        }
    }
}

// BWD: gG[N,128] (fp32) = gP @ Wcat (bf16 gPb; B = WT)
__global__ __launch_bounds__(256, 2) void gemm_bwd() {
    extern __shared__ __align__(16) char smem[];
    int tid = threadIdx.x, wid = tid >> 5, lane = tid & 31;
    int row0 = blockIdx.x * 128;
    int wm = (wid & 1) * 64, wn = (wid >> 1) * 32;
    float acc[4][4][4];
#pragma unroll
    for (int i = 0; i < 4; i++)
#pragma unroll
        for (int j = 0; j < 4; j++)
#pragma unroll
            for (int k = 0; k < 4; k++) acc[i][j][k] = 0.f;
    gemm_core(d_gPb + (size_t)row0 * PW, PW,
              d_WTb, PW,
              PW, smem, smem_to_u32(smem), tid, lane, wm, wn, acc);
    int g = lane >> 2, tg = lane & 3;
#pragma unroll
    for (int mt = 0; mt < 4; mt++) {
        int r = row0 + wm + mt * 16 + g;
#pragma unroll
        for (int nt = 0; nt < 4; nt++) {
            int cg = wn + nt * 8 + tg * 2;
            *(float2*)&d_gG[(size_t)r * DD + cg] = make_float2(acc[mt][nt][0], acc[mt][nt][1]);
            *(float2*)&d_gG[(size_t)(r + 8) * DD + cg] = make_float2(acc[mt][nt][2], acc[mt][nt][3]);
        }
    }
}

// ---------------- pair forward: 4 edges per warp (MLP batching) ----------------
__global__ __launch_bounds__(256) void s2_fwd(const int* __restrict__ c2, const int* __restrict__ u2,
                                              const float* __restrict__ a2) {
    int w = threadIdx.x >> 5, lane = threadIdx.x & 31;
    int e0 = (blockIdx.x * 8 + w) * 4;
    int c[4], u[4];
#pragma unroll
    for (int i = 0; i < 4; i++) { c[i] = c2[e0 + i]; u[i] = u2[e0 + i]; }
    float4 q[4], k[4];
#pragma unroll
    for (int i = 0; i < 4; i++) q[i] = ld_bf4(&d_Pb[(size_t)c[i] * PW + lane * 4]);
#pragma unroll
    for (int i = 0; i < 4; i++) k[i] = ld_bf4(&d_Pb[(size_t)u[i] * PW + 128 + lane * 4]);
#pragma unroll
    for (int i = 0; i < 4; i++) {
        float p = q[i].x * k[i].x + q[i].y * k[i].y + q[i].z * k[i].z + q[i].w * k[i].w;
        p += __shfl_down_sync(0xffffffffu, p, 8);
        p += __shfl_down_sync(0xffffffffu, p, 4);
        p += __shfl_down_sync(0xffffffffu, p, 2);
        p += __shfl_down_sync(0xffffffffu, p, 1);
        if ((lane & 15) == 0) {
            int h = lane >> 4;
            float s = p * 0.125f + a2[(e0 + i) * 2 + h];
            float wv = __expf(s);
            d_w2[(e0 + i) * 2 + h] = wv;
            atomicAdd(&d_z2[c[i] * 2 + h], wv);
        }
    }
}

// ---------------- motif forward: 2 motifs per warp ----------------
__global__ __launch_bounds__(256) void s3_fwd(const int* __restrict__ c3, const int* __restrict__ u3,
                                              const int* __restrict__ v3, const int* __restrict__ tt,
                                              const float* __restrict__ Tt) {
    int w = threadIdx.x >> 5, lane = threadIdx.x & 31;
    int m0 = (blockIdx.x * 8 + w) * 2;
    int c[2], u[2], v[2], t[2];
#pragma unroll
    for (int j = 0; j < 2; j++) {
        c[j] = c3[m0 + j]; u[j] = u3[m0 + j]; v[j] = v3[m0 + j]; t[j] = tt[m0 + j];
    }
    float qk[2][4], tv[2][4];
#pragma unroll
    for (int hr = 0; hr < 4; hr++) {
        int off = hr * 64 + lane * 2;
#pragma unroll
        for (int j = 0; j < 2; j++) {
            float2 qv  = ld_bf2(&d_Pb[(size_t)c[j] * PW + 256 + off]);
            float2 kuv = ld_bf2(&d_Pb[(size_t)u[j] * PW + 512 + off]);
            float2 kvv = ld_bf2(&d_Pb[(size_t)v[j] * PW + 512 + off]);
            float2 tvv = *(const float2*)&Tt[t[j] * 256 + off];
            qk[j][hr] = qv.x * kuv.x + qv.y * kuv.y;
            tv[j][hr] = tvv.x * kvv.x + tvv.y * kvv.y;
        }
    }
#pragma unroll
    for (int j = 0; j < 2; j++)
#pragma unroll
        for (int hr = 0; hr < 4; hr++) { qk[j][hr] = wsum(qk[j][hr]); tv[j][hr] = wsum(tv[j][hr]); }
    if (lane == 0) {
#pragma unroll
        for (int j = 0; j < 2; j++) {
            int m = m0 + j;
#pragma unroll
            for (int hr = 0; hr < 4; hr++) { d_qk3[m * 4 + hr] = qk[j][hr]; d_tv3[m * 4 + hr] = tv[j][hr]; }
#pragma unroll
            for (int h = 0; h < 2; h++) {
                float s = (qk[j][h * 2] * tv[j][h * 2] + qk[j][h * 2 + 1] * tv[j][h * 2 + 1]) * (1.0f / 64.0f);
                float wv = __expf(s);
                d_w3[m * 2 + h] = wv;
                atomicAdd(&d_z3[c[j] * 2 + h], wv);
            }
        }
    }
}

// ---------------- per-node memory term (fwd+bwd) + 0.5|X|^2 -> d_en ----------------
__global__ __launch_bounds__(128) void node_mem(const float* __restrict__ X) {
    __shared__ float sKm[2 * 32 * 65];
    __shared__ float sQm[4][128];
    __shared__ float sPm[4][2][32];
    int tid = threadIdx.x;
    int w = tid >> 5, lane = tid & 31;
    for (int i = tid; i < 4096; i += 128) {
        int h = i >> 11, k = (i >> 6) & 31, z = i & 63;
        sKm[(h * 32 + k) * 65 + z] = d_Km[i];
    }
    __syncthreads();
    int n = blockIdx.x * 4 + w;
    *(float4*)&sQm[w][lane * 4] = ld_bf4(&d_Pb[(size_t)n * PW + 768 + lane * 4]);
    __syncwarp();
    float smv[2];
#pragma unroll
    for (int h = 0; h < 2; h++) {
        const float* kmrow = &sKm[(h * 32 + lane) * 65];
        const float* qrow = &sQm[w][h * 64];
        float acc = 0.f;
#pragma unroll
        for (int z = 0; z < 64; z++) acc += qrow[z] * kmrow[z];
        smv[h] = acc * 0.125f;
    }
    float e_mem = 0.f;
#pragma unroll
    for (int h = 0; h < 2; h++) {
        float mx = smv[h];
#pragma unroll
        for (int o = 16; o; o >>= 1) mx = fmaxf(mx, __shfl_xor_sync(0xffffffffu, mx, o));
        float ex = __expf(smv[h] - mx);
        float zs = wsum(ex);
        e_mem -= (mx + logf(zs));          // lamm = bm = 1
        sPm[w][h][lane] = ex / zs;
    }
    __syncwarp();
#pragma unroll
    for (int h = 0; h < 2; h++)
#pragma unroll
        for (int t2 = 0; t2 < 2; t2++) {
            int z = lane + 32 * t2;
            float g = 0.f;
#pragma unroll
            for (int k = 0; k < 32; k++) g += sPm[w][h][k] * sKm[(h * 32 + k) * 65 + z];
            d_gP[(size_t)n * PW + 768 + h * 64 + z] = -0.125f * g;
        }
    float4 xv = *(const float4*)&X[n * DD + lane * 4];
    float xs = wsum(xv.x * xv.x + xv.y * xv.y + xv.z * xv.z + xv.w * xv.w);
    if (lane == 0) d_en[n] = 0.5f * xs + e_mem;
}

// ---------------- final per-graph energy (after z2/z3 complete) ----------------
__global__ __launch_bounds__(256) void eg_fin(const int* __restrict__ batch) {
    __shared__ float sE[NG];
    int tid = threadIdx.x;
    if (tid < NG) sE[tid] = 0.f;
    __syncthreads();
    int n = blockIdx.x * 256 + tid;
    float e = d_en[n];
#pragma unroll
    for (int h = 0; h < 2; h++) {
        float z2v = d_z2[n * 2 + h];
        if (z2v > 0.f) e -= logf(z2v);            // lam2 = 1
        float z3v = d_z3[n * 2 + h];
        if (z3v > 0.f) e -= 0.5f * logf(z3v);     // lam3 = 0.5
    }
    atomicAdd(&sE[batch[n]], e);
    __syncthreads();
    if (tid < NG && sE[tid] != 0.f) atomicAdd(&d_Eg[tid], sE[tid]);
}

// ---------------- pair backward: 4 edges per warp ----------------
__global__ __launch_bounds__(256) void pair_bwd(const int* __restrict__ c2, const int* __restrict__ u2) {
    int w = threadIdx.x >> 5, lane = threadIdx.x & 31;
    int e0 = (blockIdx.x * 8 + w) * 4;
    int h = lane >> 4;
    int c[4], u[4];
#pragma unroll
    for (int i = 0; i < 4; i++) { c[i] = c2[e0 + i]; u[i] = u2[e0 + i]; }
    float wv[4], zv[4];
#pragma unroll
    for (int i = 0; i < 4; i++) wv[i] = d_w2[(e0 + i) * 2 + h];
#pragma unroll
    for (int i = 0; i < 4; i++) zv[i] = d_z2[c[i] * 2 + h];
    float4 q[4], k[4];
#pragma unroll
    for (int i = 0; i < 4; i++) q[i] = ld_bf4(&d_Pb[(size_t)c[i] * PW + lane * 4]);
#pragma unroll
    for (int i = 0; i < 4; i++) k[i] = ld_bf4(&d_Pb[(size_t)u[i] * PW + 128 + lane * 4]);
#pragma unroll
    for (int i = 0; i < 4; i++) {
        float cf = -0.125f * wv[i] / zv[i];       // -lam2 * p / sqrt(HD)
        red4(&d_gP[(size_t)c[i] * PW + lane * 4], cf * k[i].x, cf * k[i].y, cf * k[i].z, cf * k[i].w);
        red4(&d_gP[(size_t)u[i] * PW + 128 + lane * 4], cf * q[i].x, cf * q[i].y, cf * q[i].z, cf * q[i].w);
    }
}

// ---------------- motif backward: 2 motifs per warp ----------------
__global__ __launch_bounds__(256) void motif_bwd(const int* __restrict__ c3, const int* __restrict__ u3,
                                                 const int* __restrict__ v3, const int* __restrict__ tt,
                                                 const float* __restrict__ Tt) {
    int w = threadIdx.x >> 5, lane = threadIdx.x & 31;
    int m0 = (blockIdx.x * 8 + w) * 2;
    int c[2], u[2], v[2], t[2];
#pragma unroll
    for (int j = 0; j < 2; j++) {
        c[j] = c3[m0 + j]; u[j] = u3[m0 + j]; v[j] = v3[m0 + j]; t[j] = tt[m0 + j];
    }
    float dqk[2][4], dtv[2][4];
#pragma unroll
    for (int j = 0; j < 2; j++) {
        int m = m0 + j;
#pragma unroll
        for (int h = 0; h < 2; h++) {
            float p = d_w3[m * 2 + h] / d_z3[c[j] * 2 + h];
            float coef = -0.5f * (1.0f / 64.0f) * p;  // -lam3 * p / HD
#pragma unroll
            for (int r = 0; r < 2; r++) {
                int hr = h * 2 + r;
                dqk[j][hr] = coef * d_tv3[m * 4 + hr];
                dtv[j][hr] = coef * d_qk3[m * 4 + hr];
            }
        }
    }
#pragma unroll
    for (int hr = 0; hr < 4; hr++) {
        int off = hr * 64 + lane * 2;
        float2 qv[2], kuv[2], kvv[2], tvv[2];
#pragma unroll
        for (int j = 0; j < 2; j++) {
            qv[j]  = ld_bf2(&d_Pb[(size_t)c[j] * PW + 256 + off]);
            kuv[j] = ld_bf2(&d_Pb[(size_t)u[j] * PW + 512 + off]);
            kvv[j] = ld_bf2(&d_Pb[(size_t)v[j] * PW + 512 + off]);
            tvv[j] = *(const float2*)&Tt[t[j] * 256 + off];
        }
#pragma unroll
        for (int j = 0; j < 2; j++) {
            red2(&d_gP[(size_t)c[j] * PW + 256 + off], dqk[j][hr] * kuv[j].x, dqk[j][hr] * kuv[j].y);
            red2(&d_gP[(size_t)u[j] * PW + 512 + off], dqk[j][hr] * qv[j].x, dqk[j][hr] * qv[j].y);
            red2(&d_gP[(size_t)v[j] * PW + 512 + off], dtv[j][hr] * tvv[j].x, dtv[j][hr] * tvv[j].y);
        }
    }
}

// ---------------- LN backward + clip + step (warp per node) ----------------
__global__ __launch_bounds__(256) void finalize(const float* __restrict__ X,
                                                const float* __restrict__ gam,
                                                const float* __restrict__ stepp,
                                                float* __restrict__ out) {
    int w = threadIdx.x >> 5, lane = threadIdx.x & 31;
    int n = blockIdx.x * 8 + w;
    float4 x  = *(const float4*)&X[n * DD + lane * 4];
    float4 gg = *(const float4*)&d_gG[n * DD + lane * 4];
    float4 gm = *(const float4*)&gam[lane * 4];
    float mu = d_mu[n], rstd = d_rstd[n];
    float xh0 = (x.x - mu) * rstd, xh1 = (x.y - mu) * rstd, xh2 = (x.z - mu) * rstd, xh3 = (x.w - mu) * rstd;
    float gx0 = gg.x * gm.x, gx1 = gg.y * gm.y, gx2 = gg.z * gm.z, gx3 = gg.w * gm.w;
    float s1 = wsum(gx0 + gx1 + gx2 + gx3) * (1.0f / 128.0f);
    float s2v = wsum(gx0 * xh0 + gx1 * xh1 + gx2 * xh2 + gx3 * xh3) * (1.0f / 128.0f);
    float g0 = x.x + rstd * (gx0 - s1 - xh0 * s2v);
    float g1 = x.y + rstd * (gx1 - s1 - xh1 * s2v);
    float g2 = x.z + rstd * (gx2 - s1 - xh2 * s2v);
    float g3 = x.w + rstd * (gx3 - s1 - xh3 * s2v);
    float gn = sqrtf(wsum(g0 * g0 + g1 * g1 + g2 * g2 + g3 * g3));
    float sc = 1.0f / fmaxf(gn, 1.0f);            // GRAD_CLIP = 1
    float st = stepp[0] * sc;                      // DAMPING = 1
    float xn0 = x.x - st * g0, xn1 = x.y - st * g1, xn2 = x.z - st * g2, xn3 = x.w - st * g3;
    float sn = sqrtf(wsum(xn0 * xn0 + xn1 * xn1 + xn2 * xn2 + xn3 * xn3));
    float sc2 = 10.0f / fmaxf(sn, 10.0f);          // STATE_CLIP = 10
    float4 o = make_float4(xn0 * sc2, xn1 * sc2, xn2 * sc2, xn3 * sc2);
    *(float4*)&out[n * DD + lane * 4] = o;
}

__global__ void eg_copy(float* __restrict__ out) {
    int t = threadIdx.x;
    if (t < NG) out[NN * DD + t] = d_Eg[t];
}

// ---------------- host launch ----------------
extern "C" void kernel_launch(void* const* d_in, const int* in_sizes, int n_in,
                              void* d_out, int out_size) {
    const float* X     = (const float*)d_in[0];
    const int*   c2    = (const int*)d_in[1];
    const int*   u2    = (const int*)d_in[2];
    const int*   c3    = (const int*)d_in[3];
    const int*   u3    = (const int*)d_in[4];
    const int*   v3    = (const int*)d_in[5];
    const int*   tt    = (const int*)d_in[6];
    const int*   batch = (const int*)d_in[7];
    const float* a2    = (const float*)d_in[8];
    const float* step  = (const float*)d_in[9];
    const float* gam   = (const float*)d_in[10];
    const float* bet   = (const float*)d_in[11];
    const float* WQ2   = (const float*)d_in[12];
    const float* WK2   = (const float*)d_in[13];
    const float* WQ3   = (const float*)d_in[14];
    const float* WK3   = (const float*)d_in[15];
    const float* Tt    = (const float*)d_in[16];
    const float* WQm   = (const float*)d_in[17];
    const float* WKm   = (const float*)d_in[18];
    const float* Bm    = (const float*)d_in[19];
    float* out = (float*)d_out;

    static cudaStream_t sE = nullptr, sM = nullptr;
    static cudaEvent_t evFork = nullptr, evE = nullptr, evM = nullptr;
    static int inited = 0;
    if (!inited) {
        cudaFuncSetAttribute(gemm_fwd, cudaFuncAttributeMaxDynamicSharedMemorySize, 2 * TILEB);
        cudaFuncSetAttribute(gemm_bwd, cudaFuncAttributeMaxDynamicSharedMemorySize, 2 * TILEB);
        cudaStreamCreateWithFlags(&sE, cudaStreamNonBlocking);
        cudaStreamCreateWithFlags(&sM, cudaStreamNonBlocking);
        cudaEventCreateWithFlags(&evFork, cudaEventDisableTiming);
        cudaEventCreateWithFlags(&evE, cudaEventDisableTiming);
        cudaEventCreateWithFlags(&evM, cudaEventDisableTiming);
        inited = 1;
    }

    void* p;
    cudaGetSymbolAddress(&p, d_gP); cudaMemsetAsync(p, 0, sizeof(float) * (size_t)NN * PW);
    cudaGetSymbolAddress(&p, d_z2); cudaMemsetAsync(p, 0, sizeof(float) * NN * 2);
    cudaGetSymbolAddress(&p, d_z3); cudaMemsetAsync(p, 0, sizeof(float) * NN * 2);
    cudaGetSymbolAddress(&p, d_Eg); cudaMemsetAsync(p, 0, sizeof(float) * NG);

    ln_fwd<<<NN / 8, 256>>>(X, gam, bet);
    prep_wcat<<<(PW * DD + 255) / 256, 256>>>(WQ2, WK2, WQ3, WK3, WQm);
    km_kernel<<<1, 256>>>(Bm, WKm);
    // Pb = bf16(G @ Wcat^T)
    gemm_fwd<<<dim3(NN / 128, PW / 128), 256, 2 * TILEB>>>();

    // fork: edge chain on sE, motif chain on sM, memory term stays on default
    cudaEventRecord(evFork, 0);
    cudaStreamWaitEvent(sE, evFork, 0);
    cudaStreamWaitEvent(sM, evFork, 0);

    s2_fwd<<<EE / 32, 256, 0, sE>>>(c2, u2, a2);
    pair_bwd<<<EE / 32, 256, 0, sE>>>(c2, u2);
    cudaEventRecord(evE, sE);

    s3_fwd<<<MMOT / 16, 256, 0, sM>>>(c3, u3, v3, tt, Tt);
    motif_bwd<<<MMOT / 16, 256, 0, sM>>>(c3, u3, v3, tt, Tt);
    cudaEventRecord(evM, sM);

    node_mem<<<NN / 4, 128>>>(X);

    // join
    cudaStreamWaitEvent(0, evE, 0);
    cudaStreamWaitEvent(0, evM, 0);

    eg_fin<<<NN / 256, 256>>>(batch);
    gp_conv<<<(NN * PW) / 1024, 256>>>();
    // gG = gP @ Wcat  (bf16 gPb; B = WT)
    gemm_bwd<<<dim3(NN / 128, 1), 256, 2 * TILEB>>>();
    finalize<<<NN / 8, 256>>>(X, gam, step, out);
    eg_copy<<<1, 32>>>(out);
}